// round 10
// baseline (speedup 1.0000x reference)
#include <cuda_runtime.h>
#include <cuda_bf16.h>
#include <cuda_fp16.h>
#include <cstdint>

#define N_NODES 100000
#define N_HE    30000
#define N_INC   300000
#define IN_CH   128
#define HID     256
#define OUT_CH  128
#define BN_EPS  1e-5f

// ---------------- device scratch (allocation-free) ----------------
__device__ float g_X1[(size_t)N_NODES * HID];   // node features (gather output)
__device__ float g_HE[(size_t)N_HE   * HID];    // hyperedge features (gather output)
__device__ float g_HEW[(size_t)N_HE  * HID];    // hyperedge features after GEMM
__device__ __half g_W1s[(size_t)HID * 2 * IN_CH];
__device__ __half g_W2s[(size_t)HID * 2 * HID];
__device__ __half g_W3s[(size_t)OUT_CH * 2 * HID];

__device__ int g_nd_cnt[N_NODES];
__device__ int g_he_cnt[N_HE];
__device__ int g_nd_off[N_NODES + 1];
__device__ int g_he_off[N_HE + 1];
__device__ int g_nd_hes[N_INC];
__device__ int g_he_nodes[N_INC];
__device__ int g_bsum[128];

__device__ float g_sum[HID];
__device__ float g_sumsq[HID];

// ---------------- helpers ----------------
__device__ __forceinline__ uint32_t smem_to_u32(const void* p) {
    uint32_t a;
    asm("{ .reg .u64 t; cvta.to.shared.u64 t, %1; cvt.u32.u64 %0, t; }" : "=r"(a) : "l"(p));
    return a;
}
#define SWZ(off) ((off) ^ (((off) >> 3) & 0x70))

__device__ __forceinline__ void cp_async16(uint32_t dst, const void* src) {
    asm volatile("cp.async.cg.shared.global [%0], [%1], 16;" :: "r"(dst), "l"(src) : "memory");
}

__device__ __forceinline__ uint32_t pack_hi2h(float x, float y) {
    __half2 h = __floats2half2_rn(x, y);
    return *reinterpret_cast<uint32_t*>(&h);
}
__device__ __forceinline__ uint32_t pack_lo2h(float x, float y, uint32_t hi2) {
    __half2 h = *reinterpret_cast<__half2*>(&hi2);
    __half2 l = __floats2half2_rn(x - __half2float(h.x), y - __half2float(h.y));
    return *reinterpret_cast<uint32_t*>(&l);
}

// ---------------- CSR build ----------------
__global__ void k_hist(const int* __restrict__ node_idx, const int* __restrict__ he_idx) {
    int i = blockIdx.x * blockDim.x + threadIdx.x;
    if (i < N_INC) {
        atomicAdd(&g_nd_cnt[node_idx[i]], 1);
        atomicAdd(&g_he_cnt[he_idx[i]], 1);
    }
}

__global__ void k_blk_sum2(int nb_nd) {
    bool he = (int)blockIdx.x >= nb_nd;
    const int* cnt = he ? g_he_cnt : g_nd_cnt;
    int n = he ? N_HE : N_NODES;
    int bid = he ? blockIdx.x - nb_nd : blockIdx.x;
    int* bs = g_bsum + (he ? 64 : 0);
    int tid = threadIdx.x;
    int base = bid * 2048;
    int s = 0;
#pragma unroll
    for (int i = 0; i < 8; i++) {
        int idx = base + i * 256 + tid;
        if (idx < n) s += cnt[idx];
    }
#pragma unroll
    for (int o = 16; o > 0; o >>= 1) s += __shfl_xor_sync(0xFFFFFFFFu, s, o);
    __shared__ int ws[8];
    if ((tid & 31) == 0) ws[tid >> 5] = s;
    __syncthreads();
    if (tid == 0) {
        int t = 0;
#pragma unroll
        for (int w = 0; w < 8; w++) t += ws[w];
        bs[bid] = t;
    }
}
__global__ void k_bsum_scan2(int nb_nd, int nb_he) {
    bool he = blockIdx.x == 1;
    int nb = he ? nb_he : nb_nd;
    int* bs = g_bsum + (he ? 64 : 0);
    int* off = he ? g_he_off : g_nd_off;
    int n = he ? N_HE : N_NODES;
    int tid = threadIdx.x;
    int lane = tid & 31, w = tid >> 5;
    int v = (tid < nb) ? bs[tid] : 0;
    int x = v;
#pragma unroll
    for (int o = 1; o < 32; o <<= 1) {
        int t = __shfl_up_sync(0xFFFFFFFFu, x, o);
        if (lane >= o) x += t;
    }
    __shared__ int ws[32];
    if (lane == 31) ws[w] = x;
    __syncthreads();
    if (w == 0) {
        int y = ws[lane];
        int z = y;
#pragma unroll
        for (int o = 1; o < 32; o <<= 1) {
            int t = __shfl_up_sync(0xFFFFFFFFu, z, o);
            if (lane >= o) z += t;
        }
        ws[lane] = z - y;
    }
    __syncthreads();
    int excl = x - v + ws[w];
    if (tid < nb) bs[tid] = excl;
    if (tid == nb - 1) off[n] = excl + v;
}
__global__ void k_blk_scan2(int nb_nd) {
    bool he = (int)blockIdx.x >= nb_nd;
    const int* cnt = he ? g_he_cnt : g_nd_cnt;
    int n = he ? N_HE : N_NODES;
    int bid = he ? blockIdx.x - nb_nd : blockIdx.x;
    const int* bs = g_bsum + (he ? 64 : 0);
    int* off = he ? g_he_off : g_nd_off;
    int tid = threadIdx.x;
    int base = bid * 2048;
    int v[8];
    int s = 0;
#pragma unroll
    for (int i = 0; i < 8; i++) {
        int idx = base + tid * 8 + i;
        v[i] = (idx < n) ? cnt[idx] : 0;
        s += v[i];
    }
    int lane = tid & 31, w = tid >> 5;
    int x = s;
#pragma unroll
    for (int o = 1; o < 32; o <<= 1) {
        int t = __shfl_up_sync(0xFFFFFFFFu, x, o);
        if (lane >= o) x += t;
    }
    __shared__ int ws[8];
    __shared__ int wexcl[8];
    if (lane == 31) ws[w] = x;
    __syncthreads();
    if (tid < 8) {
        int t = 0;
        for (int j = 0; j < tid; j++) t += ws[j];
        wexcl[tid] = t;
    }
    __syncthreads();
    int run = bs[bid] + wexcl[w] + (x - s);
#pragma unroll
    for (int i = 0; i < 8; i++) {
        int idx = base + tid * 8 + i;
        if (idx < n) off[idx] = run;
        run += v[i];
    }
}

__global__ void k_scatter(const int* __restrict__ node_idx, const int* __restrict__ he_idx) {
    int i = blockIdx.x * blockDim.x + threadIdx.x;
    if (i < N_INC) {
        int n = node_idx[i], e = he_idx[i];
        int p = atomicAdd(&g_he_cnt[e], 1);
        g_he_nodes[g_he_off[e] + p] = n;
        int q = atomicAdd(&g_nd_cnt[n], 1);
        g_nd_hes[g_nd_off[n] + q] = e;
    }
}

// ---------------- weight split ----------------
// W [K,N] fp32 -> Ws [N, 2K] fp16 (transposed), row layout [hi(K) | lo(K)]
__global__ void k_split_W(const float* __restrict__ W, __half* __restrict__ Ws, int K, int N) {
    int i = blockIdx.x * blockDim.x + threadIdx.x;
    if (i >= K * N) return;
    int k = i / N, n = i - k * N;
    float v = W[i];
    __half h = __float2half_rn(v);
    __half l = __float2half_rn(v - __half2float(h));
    __half* O = Ws + (size_t)n * 2 * K;
    O[k] = h;
    O[K + k] = l;
}

// ---------------- gemm_split: C[M,N] = A[M,K]fp32 @ W[N,2K]fp16^T ----------------
// A is split hi/lo fp16 in registers on load -> 2 smem tiles per chunk.
// Per fp32 chunk c (64 cols): logical hi chunk = c, lo chunk = c + K64 in W.
// CTA tile 128 x N, warps 4(M) x NWN, warp tile 32x64, 2-stage pipeline.
template <int NWN>
__global__ void __launch_bounds__(NWN * 128, 1)
gemm_split(const float* __restrict__ A, const __half* __restrict__ Bw,
           float* __restrict__ C, int M, int K)
{
    constexpr int N = NWN * 64;
    constexpr int NT = NWN * 128;
    constexpr uint32_t NB = (uint32_t)N * 128;
    constexpr uint32_t STAGE = 32768 + 2 * NB;
    extern __shared__ char smc[];
    const uint32_t tbase = smem_to_u32(smc);
    const int tid  = threadIdx.x;
    const int lane = tid & 31;
    const int wid  = tid >> 5;
    const int wm   = wid / NWN;
    const int wn   = wid % NWN;
    const int row0 = blockIdx.y * 128;
    const int K64  = K >> 6;
    const int Kt   = 2 * K;

    float acc[2][8][4];
#pragma unroll
    for (int i = 0; i < 2; i++)
#pragma unroll
        for (int j = 0; j < 8; j++)
#pragma unroll
            for (int k = 0; k < 4; k++) acc[i][j][k] = 0.f;

    uint32_t a_off[2], b_off[4];
#pragma unroll
    for (int mf = 0; mf < 2; mf++)
        a_off[mf] = (uint32_t)((wm * 32 + mf * 16 + (lane & 15)) * 128 + (lane >> 4) * 16);
#pragma unroll
    for (int nf4 = 0; nf4 < 4; nf4++)
        b_off[nf4] = (uint32_t)((wn * 64 + nf4 * 16 + (lane & 7) + ((lane >> 4) & 1) * 8) * 128
                                + ((lane >> 3) & 1) * 16);

    constexpr int AITERS = 1024 / NT;
    float4 af[AITERS * 2];

    auto loadA = [&](int c) {
#pragma unroll
        for (int it = 0; it < AITERS; it++) {
            int j = tid + it * NT;
            int r = j >> 3, q8 = j & 7;
            if (row0 + r < M) {
                const float* src = A + (size_t)(row0 + r) * K + c * 64 + q8 * 8;
                af[it * 2]     = *reinterpret_cast<const float4*>(src);
                af[it * 2 + 1] = *reinterpret_cast<const float4*>(src + 4);
            } else {
                af[it * 2] = make_float4(0.f, 0.f, 0.f, 0.f);
                af[it * 2 + 1] = make_float4(0.f, 0.f, 0.f, 0.f);
            }
        }
    };
    auto storeA = [&](int buf) {
#pragma unroll
        for (int it = 0; it < AITERS; it++) {
            int j = tid + it * NT;
            int r = j >> 3, q8 = j & 7;
            const float* a0 = reinterpret_cast<const float*>(&af[it * 2]);
            uint32_t h01 = pack_hi2h(a0[0], a0[1]);
            uint32_t h23 = pack_hi2h(a0[2], a0[3]);
            uint32_t h45 = pack_hi2h(a0[4], a0[5]);
            uint32_t h67 = pack_hi2h(a0[6], a0[7]);
            uint32_t l01 = pack_lo2h(a0[0], a0[1], h01);
            uint32_t l23 = pack_lo2h(a0[2], a0[3], h23);
            uint32_t l45 = pack_lo2h(a0[4], a0[5], h45);
            uint32_t l67 = pack_lo2h(a0[6], a0[7], h67);
            uint32_t off = SWZ((uint32_t)(r * 128 + q8 * 16));
            char* base = smc + buf * STAGE;
            *reinterpret_cast<uint4*>(base + off) = make_uint4(h01, h23, h45, h67);
            *reinterpret_cast<uint4*>(base + 16384 + off) = make_uint4(l01, l23, l45, l67);
        }
    };
    auto loadB = [&](int c, int buf) {
        uint32_t bb = tbase + buf * STAGE + 32768;
#pragma unroll
        for (int t = 0; t < 2; t++) {
            int cb = c + t * K64;
            const __half* Bg = Bw + cb * 64;
            for (int i = tid; i < N * 8; i += NT) {
                int r = i >> 3, q = i & 7;
                cp_async16(bb + t * NB + SWZ((uint32_t)(r * 128 + q * 16)),
                           Bg + (size_t)r * Kt + q * 8);
            }
        }
        asm volatile("cp.async.commit_group;" ::: "memory");
    };
    auto mmaStage = [&](int buf) {
#pragma unroll
        for (int t = 0; t < 2; t++) {
            uint32_t ab = tbase + buf * STAGE + t * 16384;
            uint32_t bb = tbase + buf * STAGE + 32768 + t * NB;
#pragma unroll
            for (int k16 = 0; k16 < 4; k16++) {
                uint32_t a[2][4], b[4][4];
#pragma unroll
                for (int mf = 0; mf < 2; mf++) {
                    uint32_t addr = ab + SWZ(a_off[mf] + (uint32_t)(k16 * 32));
                    asm volatile("ldmatrix.sync.aligned.m8n8.x4.shared.b16 {%0,%1,%2,%3}, [%4];"
                                 : "=r"(a[mf][0]), "=r"(a[mf][1]), "=r"(a[mf][2]), "=r"(a[mf][3])
                                 : "r"(addr));
                }
#pragma unroll
                for (int nf4 = 0; nf4 < 4; nf4++) {
                    uint32_t addr = bb + SWZ(b_off[nf4] + (uint32_t)(k16 * 32));
                    asm volatile("ldmatrix.sync.aligned.m8n8.x4.shared.b16 {%0,%1,%2,%3}, [%4];"
                                 : "=r"(b[nf4][0]), "=r"(b[nf4][1]), "=r"(b[nf4][2]), "=r"(b[nf4][3])
                                 : "r"(addr));
                }
#pragma unroll
                for (int mf = 0; mf < 2; mf++)
#pragma unroll
                    for (int nf = 0; nf < 8; nf++) {
                        asm volatile(
                            "mma.sync.aligned.m16n8k16.row.col.f32.f16.f16.f32 "
                            "{%0,%1,%2,%3}, {%4,%5,%6,%7}, {%8,%9}, {%0,%1,%2,%3};"
                            : "+f"(acc[mf][nf][0]), "+f"(acc[mf][nf][1]),
                              "+f"(acc[mf][nf][2]), "+f"(acc[mf][nf][3])
                            : "r"(a[mf][0]), "r"(a[mf][1]), "r"(a[mf][2]), "r"(a[mf][3]),
                              "r"(b[nf >> 1][(nf & 1) * 2]), "r"(b[nf >> 1][(nf & 1) * 2 + 1]));
                    }
            }
        }
    };

    loadA(0);
    loadB(0, 0);
    storeA(0);
    asm volatile("cp.async.wait_group 0;" ::: "memory");
    __syncthreads();

    for (int c = 0; c < K64; c++) {
        int buf = c & 1;
        if (c + 1 < K64) {
            loadA(c + 1);
            loadB(c + 1, buf ^ 1);
        }
        mmaStage(buf);
        if (c + 1 < K64) {
            storeA(buf ^ 1);
            asm volatile("cp.async.wait_group 0;" ::: "memory");
        }
        __syncthreads();
    }

#pragma unroll
    for (int mf = 0; mf < 2; mf++) {
        int r0g = row0 + wm * 32 + mf * 16 + (lane >> 2);
        int r1g = r0g + 8;
#pragma unroll
        for (int nf = 0; nf < 8; nf++) {
            int col = wn * 64 + nf * 8 + (lane & 3) * 2;
            float2 v0 = make_float2(acc[mf][nf][0], acc[mf][nf][1]);
            float2 v1 = make_float2(acc[mf][nf][2], acc[mf][nf][3]);
            if (r0g < M) *reinterpret_cast<float2*>(C + (size_t)r0g * N + col) = v0;
            if (r1g < M) *reinterpret_cast<float2*>(C + (size_t)r1g * N + col) = v1;
        }
    }
}

// ---------------- aggregation ----------------
// hyperedge gather with optional fused BN affine (bn applied to node features,
// commutes with the average: avg(s*x+t) = s*avg(x)+t; empty hyperedge -> 0)
__global__ void k_he_gather(const float* __restrict__ X, float* __restrict__ HE, int F4,
                            const float* __restrict__ bn_s, const float* __restrict__ bn_q,
                            const float* __restrict__ gam, const float* __restrict__ bet) {
    int e = blockIdx.x;
    int f = threadIdx.x;
    int s = g_he_off[e], t = g_he_off[e + 1];
    float4 acc = make_float4(0.f, 0.f, 0.f, 0.f);
    for (int j = s; j < t; j++) {
        int n = g_he_nodes[j];
        float4 v = reinterpret_cast<const float4*>(X)[(size_t)n * F4 + f];
        acc.x += v.x; acc.y += v.y; acc.z += v.z; acc.w += v.w;
    }
    float4 o = make_float4(0.f, 0.f, 0.f, 0.f);
    if (t > s) {
        float inv = 1.0f / (float)(t - s);
        if (bn_s) {
            const float invN = 1.0f / (float)N_NODES;
            int c = f * 4;
#pragma unroll
            for (int u = 0; u < 4; u++) {
                float m = bn_s[c + u] * invN;
                float var = bn_q[c + u] * invN - m * m;
                float sc = gam[c + u] * rsqrtf(var + BN_EPS);
                float sh = bet[c + u] - m * sc;
                float a = (&acc.x)[u] * inv;
                (&o.x)[u] = a * sc + sh;
            }
        } else {
            o.x = acc.x * inv; o.y = acc.y * inv; o.z = acc.z * inv; o.w = acc.w * inv;
        }
    }
    reinterpret_cast<float4*>(HE)[(size_t)e * F4 + f] = o;
}

// node aggregation: out = relu(Dinv * sum + bias)
__global__ void k_node_gather(const float* __restrict__ HE, const float* __restrict__ bias,
                              float* __restrict__ OUT, int F4) {
    int n = blockIdx.x;
    int f = threadIdx.x;
    int s = g_nd_off[n], t = g_nd_off[n + 1];
    float4 acc = make_float4(0.f, 0.f, 0.f, 0.f);
    for (int j = s; j < t; j++) {
        int e = g_nd_hes[j];
        float4 v = reinterpret_cast<const float4*>(HE)[(size_t)e * F4 + f];
        acc.x += v.x; acc.y += v.y; acc.z += v.z; acc.w += v.w;
    }
    float inv = (t > s) ? 1.0f / (float)(t - s) : 0.f;
    float4 b4 = reinterpret_cast<const float4*>(bias)[f];
    acc.x = fmaxf(fmaf(acc.x, inv, b4.x), 0.f);
    acc.y = fmaxf(fmaf(acc.y, inv, b4.y), 0.f);
    acc.z = fmaxf(fmaf(acc.z, inv, b4.z), 0.f);
    acc.w = fmaxf(fmaf(acc.w, inv, b4.w), 0.f);
    reinterpret_cast<float4*>(OUT)[(size_t)n * F4 + f] = acc;
}

// ---------------- batch norm stats ----------------
#define BN_ROWS_PER_BLOCK 250
__global__ void k_bn_stats(const float* __restrict__ X) {
    int f = threadIdx.x;
    int r0 = blockIdx.x * BN_ROWS_PER_BLOCK;
    float s = 0.f, ss = 0.f;
    for (int r = 0; r < BN_ROWS_PER_BLOCK; r++) {
        int row = r0 + r;
        if (row >= N_NODES) break;
        float v = X[(size_t)row * HID + f];
        s += v;
        ss += v * v;
    }
    atomicAdd(&g_sum[f], s);
    atomicAdd(&g_sumsq[f], ss);
}

// ---------------- launch ----------------
extern "C" void kernel_launch(void* const* d_in, const int* in_sizes, int n_in,
                              void* d_out, int out_size) {
    const float* x    = (const float*)d_in[0];
    const int*   edge = (const int*)d_in[1];
    const int*   node_idx = edge;
    const int*   he_idx   = edge + N_INC;
    const float* W1 = (const float*)d_in[2];
    const float* b1 = (const float*)d_in[3];
    const float* g1 = (const float*)d_in[4];
    const float* be1 = (const float*)d_in[5];
    const float* W2 = (const float*)d_in[6];
    const float* b2 = (const float*)d_in[7];
    const float* g2 = (const float*)d_in[8];
    const float* be2 = (const float*)d_in[9];
    const float* W3 = (const float*)d_in[10];
    const float* b3 = (const float*)d_in[11];
    float* out = (float*)d_out;

    void *p_X1, *p_HE, *p_HEW, *p_W1s, *p_W2s, *p_W3s;
    void *p_nd_cnt, *p_he_cnt, *p_sum, *p_sumsq;
    cudaGetSymbolAddress(&p_X1, g_X1);
    cudaGetSymbolAddress(&p_HE, g_HE);
    cudaGetSymbolAddress(&p_HEW, g_HEW);
    cudaGetSymbolAddress(&p_W1s, g_W1s);
    cudaGetSymbolAddress(&p_W2s, g_W2s);
    cudaGetSymbolAddress(&p_W3s, g_W3s);
    cudaGetSymbolAddress(&p_nd_cnt, g_nd_cnt);
    cudaGetSymbolAddress(&p_he_cnt, g_he_cnt);
    cudaGetSymbolAddress(&p_sum, g_sum);
    cudaGetSymbolAddress(&p_sumsq, g_sumsq);
    float* X1  = (float*)p_X1;
    float* HE  = (float*)p_HE;
    float* HEW = (float*)p_HEW;
    __half* W1s = (__half*)p_W1s;
    __half* W2s = (__half*)p_W2s;
    __half* W3s = (__half*)p_W3s;
    float* bn_s = (float*)p_sum;
    float* bn_q = (float*)p_sumsq;

    const int GEMM_SMEM_N256 = 2 * (32768 + 2 * 256 * 128);   // 196608
    const int GEMM_SMEM_N128 = 2 * (32768 + 2 * 128 * 128);   // 131072
    cudaFuncSetAttribute(gemm_split<4>, cudaFuncAttributeMaxDynamicSharedMemorySize, GEMM_SMEM_N256);
    cudaFuncSetAttribute(gemm_split<2>, cudaFuncAttributeMaxDynamicSharedMemorySize, GEMM_SMEM_N128);
    const int he_tiles = (N_HE + 127) / 128;   // 235

    // ---- weight splits ----
    k_split_W<<<(IN_CH * HID + 255) / 256, 256>>>(W1, W1s, IN_CH, HID);
    k_split_W<<<(HID * HID + 255) / 256, 256>>>(W2, W2s, HID, HID);
    k_split_W<<<(HID * OUT_CH + 255) / 256, 256>>>(W3, W3s, HID, OUT_CH);

    // ---- CSR build ----
    cudaMemsetAsync(p_nd_cnt, 0, N_NODES * sizeof(int));
    cudaMemsetAsync(p_he_cnt, 0, N_HE * sizeof(int));
    k_hist<<<(N_INC + 255) / 256, 256>>>(node_idx, he_idx);
    const int nb_nd = (N_NODES + 2047) / 2048;
    const int nb_he = (N_HE + 2047) / 2048;
    k_blk_sum2<<<nb_nd + nb_he, 256>>>(nb_nd);
    k_bsum_scan2<<<2, 1024>>>(nb_nd, nb_he);
    k_blk_scan2<<<nb_nd + nb_he, 256>>>(nb_nd);
    cudaMemsetAsync(p_nd_cnt, 0, N_NODES * sizeof(int));
    cudaMemsetAsync(p_he_cnt, 0, N_HE * sizeof(int));
    k_scatter<<<(N_INC + 255) / 256, 256>>>(node_idx, he_idx);

    const int bn_grid = (N_NODES + BN_ROWS_PER_BLOCK - 1) / BN_ROWS_PER_BLOCK;

    // ---- layer 1: he_gather(x) -> GEMM(30k) -> node_gather(+b1,relu) -> bn_stats ----
    {
        k_he_gather<<<N_HE, IN_CH / 4>>>(x, HE, IN_CH / 4, nullptr, nullptr, nullptr, nullptr);
        dim3 grid(1, he_tiles);
        gemm_split<4><<<grid, 512, GEMM_SMEM_N256>>>(HE, W1s, HEW, N_HE, IN_CH);
        k_node_gather<<<N_NODES, HID / 4>>>(HEW, b1, X1, HID / 4);
        cudaMemsetAsync(p_sum, 0, HID * sizeof(float));
        cudaMemsetAsync(p_sumsq, 0, HID * sizeof(float));
        k_bn_stats<<<bn_grid, HID>>>(X1);
    }
    // ---- layer 2: he_gather(BN1 fused) -> GEMM(30k) -> node_gather -> bn_stats ----
    {
        k_he_gather<<<N_HE, HID / 4>>>(X1, HE, HID / 4, bn_s, bn_q, g1, be1);
        dim3 grid(1, he_tiles);
        gemm_split<4><<<grid, 512, GEMM_SMEM_N256>>>(HE, W2s, HEW, N_HE, HID);
        k_node_gather<<<N_NODES, HID / 4>>>(HEW, b2, X1, HID / 4);
        cudaMemsetAsync(p_sum, 0, HID * sizeof(float));
        cudaMemsetAsync(p_sumsq, 0, HID * sizeof(float));
        k_bn_stats<<<bn_grid, HID>>>(X1);
    }
    // ---- layer 3: he_gather(BN2 fused) -> GEMM(30k, N=128) -> node_gather -> out ----
    {
        k_he_gather<<<N_HE, HID / 4>>>(X1, HE, HID / 4, bn_s, bn_q, g2, be2);
        dim3 grid(1, he_tiles);
        gemm_split<2><<<grid, 256, GEMM_SMEM_N128>>>(HE, W3s, HEW, N_HE, HID);
        k_node_gather<<<N_NODES, OUT_CH / 4>>>(HEW, b3, out, OUT_CH / 4);
    }
}

// round 11
// speedup vs baseline: 1.6766x; 1.6766x over previous
#include <cuda_runtime.h>
#include <cuda_bf16.h>
#include <cuda_fp16.h>
#include <cstdint>

#define N_NODES 100000
#define N_HE    30000
#define N_INC   300000
#define IN_CH   128
#define HID     256
#define OUT_CH  128
#define BN_EPS  1e-5f

// ---------------- device scratch (allocation-free) ----------------
__device__ float g_X1[(size_t)N_NODES * HID];   // node features (gather output)
__device__ float g_HE[(size_t)N_HE   * HID];    // hyperedge features (gather output)
__device__ float g_HEW[(size_t)N_HE  * HID];    // hyperedge features after GEMM
__device__ __half g_W1s[(size_t)HID * 2 * IN_CH];
__device__ __half g_W2s[(size_t)HID * 2 * HID];
__device__ __half g_W3s[(size_t)OUT_CH * 2 * HID];

__device__ int g_nd_cnt[N_NODES];
__device__ int g_he_cnt[N_HE];
__device__ int g_nd_off[N_NODES + 1];
__device__ int g_he_off[N_HE + 1];
__device__ int g_nd_hes[N_INC];
__device__ int g_he_nodes[N_INC];
__device__ int g_bsum[128];

__device__ float g_sum[HID];
__device__ float g_sumsq[HID];

// ---------------- helpers ----------------
__device__ __forceinline__ uint32_t smem_to_u32(const void* p) {
    uint32_t a;
    asm("{ .reg .u64 t; cvta.to.shared.u64 t, %1; cvt.u32.u64 %0, t; }" : "=r"(a) : "l"(p));
    return a;
}
#define SWZ(off) ((off) ^ (((off) >> 3) & 0x70))

__device__ __forceinline__ void cp_async16(uint32_t dst, const void* src) {
    asm volatile("cp.async.cg.shared.global [%0], [%1], 16;" :: "r"(dst), "l"(src) : "memory");
}

__device__ __forceinline__ uint32_t pack_hi2h(float x, float y) {
    __half2 h = __floats2half2_rn(x, y);
    return *reinterpret_cast<uint32_t*>(&h);
}
__device__ __forceinline__ uint32_t pack_lo2h(float x, float y, uint32_t hi2) {
    __half2 h = *reinterpret_cast<__half2*>(&hi2);
    __half2 l = __floats2half2_rn(x - __half2float(h.x), y - __half2float(h.y));
    return *reinterpret_cast<uint32_t*>(&l);
}

// ---------------- CSR build ----------------
__global__ void k_hist(const int* __restrict__ node_idx, const int* __restrict__ he_idx) {
    int i = blockIdx.x * blockDim.x + threadIdx.x;
    if (i < N_INC) {
        atomicAdd(&g_nd_cnt[node_idx[i]], 1);
        atomicAdd(&g_he_cnt[he_idx[i]], 1);
    }
}

__global__ void k_blk_sum2(int nb_nd) {
    bool he = (int)blockIdx.x >= nb_nd;
    const int* cnt = he ? g_he_cnt : g_nd_cnt;
    int n = he ? N_HE : N_NODES;
    int bid = he ? blockIdx.x - nb_nd : blockIdx.x;
    int* bs = g_bsum + (he ? 64 : 0);
    int tid = threadIdx.x;
    int base = bid * 2048;
    int s = 0;
#pragma unroll
    for (int i = 0; i < 8; i++) {
        int idx = base + i * 256 + tid;
        if (idx < n) s += cnt[idx];
    }
#pragma unroll
    for (int o = 16; o > 0; o >>= 1) s += __shfl_xor_sync(0xFFFFFFFFu, s, o);
    __shared__ int ws[8];
    if ((tid & 31) == 0) ws[tid >> 5] = s;
    __syncthreads();
    if (tid == 0) {
        int t = 0;
#pragma unroll
        for (int w = 0; w < 8; w++) t += ws[w];
        bs[bid] = t;
    }
}
__global__ void k_bsum_scan2(int nb_nd, int nb_he) {
    bool he = blockIdx.x == 1;
    int nb = he ? nb_he : nb_nd;
    int* bs = g_bsum + (he ? 64 : 0);
    int* off = he ? g_he_off : g_nd_off;
    int n = he ? N_HE : N_NODES;
    int tid = threadIdx.x;
    int lane = tid & 31, w = tid >> 5;
    int v = (tid < nb) ? bs[tid] : 0;
    int x = v;
#pragma unroll
    for (int o = 1; o < 32; o <<= 1) {
        int t = __shfl_up_sync(0xFFFFFFFFu, x, o);
        if (lane >= o) x += t;
    }
    __shared__ int ws[32];
    if (lane == 31) ws[w] = x;
    __syncthreads();
    if (w == 0) {
        int y = ws[lane];
        int z = y;
#pragma unroll
        for (int o = 1; o < 32; o <<= 1) {
            int t = __shfl_up_sync(0xFFFFFFFFu, z, o);
            if (lane >= o) z += t;
        }
        ws[lane] = z - y;
    }
    __syncthreads();
    int excl = x - v + ws[w];
    if (tid < nb) bs[tid] = excl;
    if (tid == nb - 1) off[n] = excl + v;
}
__global__ void k_blk_scan2(int nb_nd) {
    bool he = (int)blockIdx.x >= nb_nd;
    const int* cnt = he ? g_he_cnt : g_nd_cnt;
    int n = he ? N_HE : N_NODES;
    int bid = he ? blockIdx.x - nb_nd : blockIdx.x;
    const int* bs = g_bsum + (he ? 64 : 0);
    int* off = he ? g_he_off : g_nd_off;
    int tid = threadIdx.x;
    int base = bid * 2048;
    int v[8];
    int s = 0;
#pragma unroll
    for (int i = 0; i < 8; i++) {
        int idx = base + tid * 8 + i;
        v[i] = (idx < n) ? cnt[idx] : 0;
        s += v[i];
    }
    int lane = tid & 31, w = tid >> 5;
    int x = s;
#pragma unroll
    for (int o = 1; o < 32; o <<= 1) {
        int t = __shfl_up_sync(0xFFFFFFFFu, x, o);
        if (lane >= o) x += t;
    }
    __shared__ int ws[8];
    __shared__ int wexcl[8];
    if (lane == 31) ws[w] = x;
    __syncthreads();
    if (tid < 8) {
        int t = 0;
        for (int j = 0; j < tid; j++) t += ws[j];
        wexcl[tid] = t;
    }
    __syncthreads();
    int run = bs[bid] + wexcl[w] + (x - s);
#pragma unroll
    for (int i = 0; i < 8; i++) {
        int idx = base + tid * 8 + i;
        if (idx < n) off[idx] = run;
        run += v[i];
    }
}

__global__ void k_scatter(const int* __restrict__ node_idx, const int* __restrict__ he_idx) {
    int i = blockIdx.x * blockDim.x + threadIdx.x;
    if (i < N_INC) {
        int n = node_idx[i], e = he_idx[i];
        int p = atomicAdd(&g_he_cnt[e], 1);
        g_he_nodes[g_he_off[e] + p] = n;
        int q = atomicAdd(&g_nd_cnt[n], 1);
        g_nd_hes[g_nd_off[n] + q] = e;
    }
}

// ---------------- weight split ----------------
__global__ void k_split_W(const float* __restrict__ W, __half* __restrict__ Ws, int K, int N) {
    int i = blockIdx.x * blockDim.x + threadIdx.x;
    if (i >= K * N) return;
    int k = i / N, n = i - k * N;
    float v = W[i];
    __half h = __float2half_rn(v);
    __half l = __float2half_rn(v - __half2float(h));
    __half* O = Ws + (size_t)n * 2 * K;
    O[k] = h;
    O[K + k] = l;
}

// ---------------- gemm_split: C[M,N] = A[M,K]fp32 @ W[N,2K]fp16^T ----------------
template <int NWN>
__global__ void __launch_bounds__(NWN * 128, 1)
gemm_split(const float* __restrict__ A, const __half* __restrict__ Bw,
           float* __restrict__ C, int M, int K)
{
    constexpr int N = NWN * 64;
    constexpr int NT = NWN * 128;
    constexpr uint32_t NB = (uint32_t)N * 128;
    constexpr uint32_t STAGE = 32768 + 2 * NB;
    extern __shared__ char smc[];
    const uint32_t tbase = smem_to_u32(smc);
    const int tid  = threadIdx.x;
    const int lane = tid & 31;
    const int wid  = tid >> 5;
    const int wm   = wid / NWN;
    const int wn   = wid % NWN;
    const int row0 = blockIdx.y * 128;
    const int K64  = K >> 6;
    const int Kt   = 2 * K;

    float acc[2][8][4];
#pragma unroll
    for (int i = 0; i < 2; i++)
#pragma unroll
        for (int j = 0; j < 8; j++)
#pragma unroll
            for (int k = 0; k < 4; k++) acc[i][j][k] = 0.f;

    uint32_t a_off[2], b_off[4];
#pragma unroll
    for (int mf = 0; mf < 2; mf++)
        a_off[mf] = (uint32_t)((wm * 32 + mf * 16 + (lane & 15)) * 128 + (lane >> 4) * 16);
#pragma unroll
    for (int nf4 = 0; nf4 < 4; nf4++)
        b_off[nf4] = (uint32_t)((wn * 64 + nf4 * 16 + (lane & 7) + ((lane >> 4) & 1) * 8) * 128
                                + ((lane >> 3) & 1) * 16);

    constexpr int AITERS = 1024 / NT;
    float4 af[AITERS * 2];

    auto loadA = [&](int c) {
#pragma unroll
        for (int it = 0; it < AITERS; it++) {
            int j = tid + it * NT;
            int r = j >> 3, q8 = j & 7;
            if (row0 + r < M) {
                const float* src = A + (size_t)(row0 + r) * K + c * 64 + q8 * 8;
                af[it * 2]     = *reinterpret_cast<const float4*>(src);
                af[it * 2 + 1] = *reinterpret_cast<const float4*>(src + 4);
            } else {
                af[it * 2] = make_float4(0.f, 0.f, 0.f, 0.f);
                af[it * 2 + 1] = make_float4(0.f, 0.f, 0.f, 0.f);
            }
        }
    };
    auto storeA = [&](int buf) {
#pragma unroll
        for (int it = 0; it < AITERS; it++) {
            int j = tid + it * NT;
            int r = j >> 3, q8 = j & 7;
            const float* a0 = reinterpret_cast<const float*>(&af[it * 2]);
            uint32_t h01 = pack_hi2h(a0[0], a0[1]);
            uint32_t h23 = pack_hi2h(a0[2], a0[3]);
            uint32_t h45 = pack_hi2h(a0[4], a0[5]);
            uint32_t h67 = pack_hi2h(a0[6], a0[7]);
            uint32_t l01 = pack_lo2h(a0[0], a0[1], h01);
            uint32_t l23 = pack_lo2h(a0[2], a0[3], h23);
            uint32_t l45 = pack_lo2h(a0[4], a0[5], h45);
            uint32_t l67 = pack_lo2h(a0[6], a0[7], h67);
            uint32_t off = SWZ((uint32_t)(r * 128 + q8 * 16));
            char* base = smc + buf * STAGE;
            *reinterpret_cast<uint4*>(base + off) = make_uint4(h01, h23, h45, h67);
            *reinterpret_cast<uint4*>(base + 16384 + off) = make_uint4(l01, l23, l45, l67);
        }
    };
    auto loadB = [&](int c, int buf) {
        uint32_t bb = tbase + buf * STAGE + 32768;
#pragma unroll
        for (int t = 0; t < 2; t++) {
            int cb = c + t * K64;
            const __half* Bg = Bw + cb * 64;
            for (int i = tid; i < N * 8; i += NT) {
                int r = i >> 3, q = i & 7;
                cp_async16(bb + t * NB + SWZ((uint32_t)(r * 128 + q * 16)),
                           Bg + (size_t)r * Kt + q * 8);
            }
        }
        asm volatile("cp.async.commit_group;" ::: "memory");
    };
    auto mmaStage = [&](int buf) {
#pragma unroll
        for (int t = 0; t < 2; t++) {
            uint32_t ab = tbase + buf * STAGE + t * 16384;
            uint32_t bb = tbase + buf * STAGE + 32768 + t * NB;
#pragma unroll
            for (int k16 = 0; k16 < 4; k16++) {
                uint32_t a[2][4], b[4][4];
#pragma unroll
                for (int mf = 0; mf < 2; mf++) {
                    uint32_t addr = ab + SWZ(a_off[mf] + (uint32_t)(k16 * 32));
                    asm volatile("ldmatrix.sync.aligned.m8n8.x4.shared.b16 {%0,%1,%2,%3}, [%4];"
                                 : "=r"(a[mf][0]), "=r"(a[mf][1]), "=r"(a[mf][2]), "=r"(a[mf][3])
                                 : "r"(addr));
                }
#pragma unroll
                for (int nf4 = 0; nf4 < 4; nf4++) {
                    uint32_t addr = bb + SWZ(b_off[nf4] + (uint32_t)(k16 * 32));
                    asm volatile("ldmatrix.sync.aligned.m8n8.x4.shared.b16 {%0,%1,%2,%3}, [%4];"
                                 : "=r"(b[nf4][0]), "=r"(b[nf4][1]), "=r"(b[nf4][2]), "=r"(b[nf4][3])
                                 : "r"(addr));
                }
#pragma unroll
                for (int mf = 0; mf < 2; mf++)
#pragma unroll
                    for (int nf = 0; nf < 8; nf++) {
                        asm volatile(
                            "mma.sync.aligned.m16n8k16.row.col.f32.f16.f16.f32 "
                            "{%0,%1,%2,%3}, {%4,%5,%6,%7}, {%8,%9}, {%0,%1,%2,%3};"
                            : "+f"(acc[mf][nf][0]), "+f"(acc[mf][nf][1]),
                              "+f"(acc[mf][nf][2]), "+f"(acc[mf][nf][3])
                            : "r"(a[mf][0]), "r"(a[mf][1]), "r"(a[mf][2]), "r"(a[mf][3]),
                              "r"(b[nf >> 1][(nf & 1) * 2]), "r"(b[nf >> 1][(nf & 1) * 2 + 1]));
                    }
            }
        }
    };

    loadA(0);
    loadB(0, 0);
    storeA(0);
    asm volatile("cp.async.wait_group 0;" ::: "memory");
    __syncthreads();

    for (int c = 0; c < K64; c++) {
        int buf = c & 1;
        if (c + 1 < K64) {
            loadA(c + 1);
            loadB(c + 1, buf ^ 1);
        }
        mmaStage(buf);
        if (c + 1 < K64) {
            storeA(buf ^ 1);
            asm volatile("cp.async.wait_group 0;" ::: "memory");
        }
        __syncthreads();
    }

#pragma unroll
    for (int mf = 0; mf < 2; mf++) {
        int r0g = row0 + wm * 32 + mf * 16 + (lane >> 2);
        int r1g = r0g + 8;
#pragma unroll
        for (int nf = 0; nf < 8; nf++) {
            int col = wn * 64 + nf * 8 + (lane & 3) * 2;
            float2 v0 = make_float2(acc[mf][nf][0], acc[mf][nf][1]);
            float2 v1 = make_float2(acc[mf][nf][2], acc[mf][nf][3]);
            if (r0g < M) *reinterpret_cast<float2*>(C + (size_t)r0g * N + col) = v0;
            if (r1g < M) *reinterpret_cast<float2*>(C + (size_t)r1g * N + col) = v1;
        }
    }
}

// ---------------- aggregation ----------------
// hyperedge gather, F=128, no BN (layer 1). 256 thr: 8 edges in flight, 32 edges/blk.
__global__ void __launch_bounds__(256) k_he_gather128(const float* __restrict__ X,
                                                      float* __restrict__ HE) {
    int tid = threadIdx.x;
    int f4 = tid & 31;
    int sub = tid >> 5;              // 0..7
    int base = blockIdx.x * 32;
#pragma unroll
    for (int i = 0; i < 4; i++) {
        int e = base + i * 8 + sub;
        if (e >= N_HE) break;
        int s = g_he_off[e], t = g_he_off[e + 1];
        float4 acc = make_float4(0.f, 0.f, 0.f, 0.f);
        for (int j = s; j < t; j++) {
            int n = g_he_nodes[j];
            float4 v = reinterpret_cast<const float4*>(X)[(size_t)n * 32 + f4];
            acc.x += v.x; acc.y += v.y; acc.z += v.z; acc.w += v.w;
        }
        float4 o = make_float4(0.f, 0.f, 0.f, 0.f);
        if (t > s) {
            float inv = 1.0f / (float)(t - s);
            o.x = acc.x * inv; o.y = acc.y * inv; o.z = acc.z * inv; o.w = acc.w * inv;
        }
        reinterpret_cast<float4*>(HE)[(size_t)e * 32 + f4] = o;
    }
}

// hyperedge gather, F=256, BN affine fused (layers 2/3). 4 edges in flight, 16/blk.
__global__ void __launch_bounds__(256) k_he_gather_bn(const float* __restrict__ X,
                                                      float* __restrict__ HE,
                                                      const float* __restrict__ gam,
                                                      const float* __restrict__ bet) {
    int tid = threadIdx.x;
    int f4 = tid & 63;
    int sub = tid >> 6;              // 0..3
    int c = f4 * 4;
    // per-thread BN scale/shift for 4 channels
    const float invN = 1.0f / (float)N_NODES;
    float sc[4], sh[4];
#pragma unroll
    for (int u = 0; u < 4; u++) {
        float m = g_sum[c + u] * invN;
        float var = g_sumsq[c + u] * invN - m * m;
        float s = gam[c + u] * rsqrtf(var + BN_EPS);
        sc[u] = s;
        sh[u] = bet[c + u] - m * s;
    }
    int base = blockIdx.x * 16;
#pragma unroll
    for (int i = 0; i < 4; i++) {
        int e = base + i * 4 + sub;
        if (e >= N_HE) break;
        int s = g_he_off[e], t = g_he_off[e + 1];
        float4 acc = make_float4(0.f, 0.f, 0.f, 0.f);
        for (int j = s; j < t; j++) {
            int n = g_he_nodes[j];
            float4 v = reinterpret_cast<const float4*>(X)[(size_t)n * 64 + f4];
            acc.x += v.x; acc.y += v.y; acc.z += v.z; acc.w += v.w;
        }
        float4 o = make_float4(0.f, 0.f, 0.f, 0.f);
        if (t > s) {
            float inv = 1.0f / (float)(t - s);
            o.x = (acc.x * inv) * sc[0] + sh[0];
            o.y = (acc.y * inv) * sc[1] + sh[1];
            o.z = (acc.z * inv) * sc[2] + sh[2];
            o.w = (acc.w * inv) * sc[3] + sh[3];
        }
        reinterpret_cast<float4*>(HE)[(size_t)e * 64 + f4] = o;
    }
}

// node gather F=256 + bias + relu + fused BN-stats accumulation (layers 1/2).
// 256 thr: 4 nodes in flight, 128 nodes/blk; block-local Σ/Σ² then one atomic/ch.
__global__ void __launch_bounds__(256) k_node_gather_bn(const float* __restrict__ HEW,
                                                        const float* __restrict__ bias,
                                                        float* __restrict__ OUT) {
    __shared__ float rs[4][HID];
    __shared__ float rq[4][HID];
    int tid = threadIdx.x;
    int f4 = tid & 63;
    int sub = tid >> 6;              // 0..3
    int c = f4 * 4;
    float4 b4 = reinterpret_cast<const float4*>(bias)[f4];
    float s4[4] = {0.f, 0.f, 0.f, 0.f};
    float q4[4] = {0.f, 0.f, 0.f, 0.f};
    int base = blockIdx.x * 128;
#pragma unroll 4
    for (int i = 0; i < 32; i++) {
        int n = base + i * 4 + sub;
        if (n >= N_NODES) break;
        int s = g_nd_off[n], t = g_nd_off[n + 1];
        float4 acc = make_float4(0.f, 0.f, 0.f, 0.f);
        for (int j = s; j < t; j++) {
            int e = g_nd_hes[j];
            float4 v = reinterpret_cast<const float4*>(HEW)[(size_t)e * 64 + f4];
            acc.x += v.x; acc.y += v.y; acc.z += v.z; acc.w += v.w;
        }
        float inv = (t > s) ? 1.0f / (float)(t - s) : 0.f;
        float4 o;
        o.x = fmaxf(fmaf(acc.x, inv, b4.x), 0.f);
        o.y = fmaxf(fmaf(acc.y, inv, b4.y), 0.f);
        o.z = fmaxf(fmaf(acc.z, inv, b4.z), 0.f);
        o.w = fmaxf(fmaf(acc.w, inv, b4.w), 0.f);
        reinterpret_cast<float4*>(OUT)[(size_t)n * 64 + f4] = o;
        s4[0] += o.x; s4[1] += o.y; s4[2] += o.z; s4[3] += o.w;
        q4[0] += o.x * o.x; q4[1] += o.y * o.y; q4[2] += o.z * o.z; q4[3] += o.w * o.w;
    }
#pragma unroll
    for (int u = 0; u < 4; u++) {
        rs[sub][c + u] = s4[u];
        rq[sub][c + u] = q4[u];
    }
    __syncthreads();
    if (sub == 0) {
#pragma unroll
        for (int u = 0; u < 4; u++) {
            float ts = rs[0][c + u] + rs[1][c + u] + rs[2][c + u] + rs[3][c + u];
            float tq = rq[0][c + u] + rq[1][c + u] + rq[2][c + u] + rq[3][c + u];
            atomicAdd(&g_sum[c + u], ts);
            atomicAdd(&g_sumsq[c + u], tq);
        }
    }
}

// node gather F=128 + bias + relu (layer 3 -> out). 8 nodes in flight, 128/blk.
__global__ void __launch_bounds__(256) k_node_gather128(const float* __restrict__ HEW,
                                                        const float* __restrict__ bias,
                                                        float* __restrict__ OUT) {
    int tid = threadIdx.x;
    int f4 = tid & 31;
    int sub = tid >> 5;              // 0..7
    float4 b4 = reinterpret_cast<const float4*>(bias)[f4];
    int base = blockIdx.x * 128;
#pragma unroll 4
    for (int i = 0; i < 16; i++) {
        int n = base + i * 8 + sub;
        if (n >= N_NODES) break;
        int s = g_nd_off[n], t = g_nd_off[n + 1];
        float4 acc = make_float4(0.f, 0.f, 0.f, 0.f);
        for (int j = s; j < t; j++) {
            int e = g_nd_hes[j];
            float4 v = reinterpret_cast<const float4*>(HEW)[(size_t)e * 32 + f4];
            acc.x += v.x; acc.y += v.y; acc.z += v.z; acc.w += v.w;
        }
        float inv = (t > s) ? 1.0f / (float)(t - s) : 0.f;
        float4 o;
        o.x = fmaxf(fmaf(acc.x, inv, b4.x), 0.f);
        o.y = fmaxf(fmaf(acc.y, inv, b4.y), 0.f);
        o.z = fmaxf(fmaf(acc.z, inv, b4.z), 0.f);
        o.w = fmaxf(fmaf(acc.w, inv, b4.w), 0.f);
        reinterpret_cast<float4*>(OUT)[(size_t)n * 32 + f4] = o;
    }
}

// ---------------- launch ----------------
extern "C" void kernel_launch(void* const* d_in, const int* in_sizes, int n_in,
                              void* d_out, int out_size) {
    const float* x    = (const float*)d_in[0];
    const int*   edge = (const int*)d_in[1];
    const int*   node_idx = edge;
    const int*   he_idx   = edge + N_INC;
    const float* W1 = (const float*)d_in[2];
    const float* b1 = (const float*)d_in[3];
    const float* g1 = (const float*)d_in[4];
    const float* be1 = (const float*)d_in[5];
    const float* W2 = (const float*)d_in[6];
    const float* b2 = (const float*)d_in[7];
    const float* g2 = (const float*)d_in[8];
    const float* be2 = (const float*)d_in[9];
    const float* W3 = (const float*)d_in[10];
    const float* b3 = (const float*)d_in[11];
    float* out = (float*)d_out;

    void *p_X1, *p_HE, *p_HEW, *p_W1s, *p_W2s, *p_W3s;
    void *p_nd_cnt, *p_he_cnt, *p_sum, *p_sumsq;
    cudaGetSymbolAddress(&p_X1, g_X1);
    cudaGetSymbolAddress(&p_HE, g_HE);
    cudaGetSymbolAddress(&p_HEW, g_HEW);
    cudaGetSymbolAddress(&p_W1s, g_W1s);
    cudaGetSymbolAddress(&p_W2s, g_W2s);
    cudaGetSymbolAddress(&p_W3s, g_W3s);
    cudaGetSymbolAddress(&p_nd_cnt, g_nd_cnt);
    cudaGetSymbolAddress(&p_he_cnt, g_he_cnt);
    cudaGetSymbolAddress(&p_sum, g_sum);
    cudaGetSymbolAddress(&p_sumsq, g_sumsq);
    float* X1  = (float*)p_X1;
    float* HE  = (float*)p_HE;
    float* HEW = (float*)p_HEW;
    __half* W1s = (__half*)p_W1s;
    __half* W2s = (__half*)p_W2s;
    __half* W3s = (__half*)p_W3s;

    const int GEMM_SMEM_N256 = 2 * (32768 + 2 * 256 * 128);   // 196608
    const int GEMM_SMEM_N128 = 2 * (32768 + 2 * 128 * 128);   // 131072
    cudaFuncSetAttribute(gemm_split<4>, cudaFuncAttributeMaxDynamicSharedMemorySize, GEMM_SMEM_N256);
    cudaFuncSetAttribute(gemm_split<2>, cudaFuncAttributeMaxDynamicSharedMemorySize, GEMM_SMEM_N128);
    const int he_tiles = (N_HE + 127) / 128;      // 235
    const int he_g128 = (N_HE + 31) / 32;         // 938
    const int he_g256 = (N_HE + 15) / 16;         // 1875
    const int nd_g = (N_NODES + 127) / 128;       // 782

    // ---- weight splits ----
    k_split_W<<<(IN_CH * HID + 255) / 256, 256>>>(W1, W1s, IN_CH, HID);
    k_split_W<<<(HID * HID + 255) / 256, 256>>>(W2, W2s, HID, HID);
    k_split_W<<<(HID * OUT_CH + 255) / 256, 256>>>(W3, W3s, HID, OUT_CH);

    // ---- CSR build ----
    cudaMemsetAsync(p_nd_cnt, 0, N_NODES * sizeof(int));
    cudaMemsetAsync(p_he_cnt, 0, N_HE * sizeof(int));
    k_hist<<<(N_INC + 255) / 256, 256>>>(node_idx, he_idx);
    const int nb_nd = (N_NODES + 2047) / 2048;
    const int nb_he = (N_HE + 2047) / 2048;
    k_blk_sum2<<<nb_nd + nb_he, 256>>>(nb_nd);
    k_bsum_scan2<<<2, 1024>>>(nb_nd, nb_he);
    k_blk_scan2<<<nb_nd + nb_he, 256>>>(nb_nd);
    cudaMemsetAsync(p_nd_cnt, 0, N_NODES * sizeof(int));
    cudaMemsetAsync(p_he_cnt, 0, N_HE * sizeof(int));
    k_scatter<<<(N_INC + 255) / 256, 256>>>(node_idx, he_idx);

    // ---- layer 1: he_gather(x) -> GEMM(30k) -> node_gather+bn_stats ----
    {
        k_he_gather128<<<he_g128, 256>>>(x, HE);
        dim3 grid(1, he_tiles);
        gemm_split<4><<<grid, 512, GEMM_SMEM_N256>>>(HE, W1s, HEW, N_HE, IN_CH);
        cudaMemsetAsync(p_sum, 0, HID * sizeof(float));
        cudaMemsetAsync(p_sumsq, 0, HID * sizeof(float));
        k_node_gather_bn<<<nd_g, 256>>>(HEW, b1, X1);
    }
    // ---- layer 2: he_gather(BN1 fused) -> GEMM(30k) -> node_gather+bn_stats ----
    {
        k_he_gather_bn<<<he_g256, 256>>>(X1, HE, g1, be1);
        dim3 grid(1, he_tiles);
        gemm_split<4><<<grid, 512, GEMM_SMEM_N256>>>(HE, W2s, HEW, N_HE, HID);
        cudaMemsetAsync(p_sum, 0, HID * sizeof(float));
        cudaMemsetAsync(p_sumsq, 0, HID * sizeof(float));
        k_node_gather_bn<<<nd_g, 256>>>(HEW, b2, X1);
    }
    // ---- layer 3: he_gather(BN2 fused) -> GEMM(30k, N=128) -> node_gather -> out ----
    {
        k_he_gather_bn<<<he_g256, 256>>>(X1, HE, g2, be2);
        dim3 grid(1, he_tiles);
        gemm_split<2><<<grid, 256, GEMM_SMEM_N128>>>(HE, W3s, HEW, N_HE, HID);
        k_node_gather128<<<nd_g, 256>>>(HEW, b3, out);
    }
}

// round 12
// speedup vs baseline: 2.0848x; 1.2434x over previous
#include <cuda_runtime.h>
#include <cuda_bf16.h>
#include <cuda_fp16.h>
#include <cstdint>

#define N_NODES 100000
#define N_HE    30000
#define N_INC   300000
#define IN_CH   128
#define HID     256
#define OUT_CH  128
#define BN_EPS  1e-5f

// ---------------- device scratch (allocation-free, zero-initialized) ----------------
__device__ __half g_X1[(size_t)N_NODES * HID];          // node features fp16
__device__ __half g_HE[(size_t)(N_HE + 128) * HID];     // hyperedge features fp16 (padded)
__device__ __half g_HEW[(size_t)N_HE * HID];            // hyperedge features after GEMM fp16
__device__ __half g_W1s[(size_t)HID * 2 * IN_CH];       // [256, 256] = [hi(128)|lo(128)]
__device__ __half g_W2s[(size_t)HID * 2 * HID];         // [256, 512]
__device__ __half g_W3s[(size_t)OUT_CH * 2 * HID];      // [128, 512]

__device__ int g_nd_cnt[N_NODES];
__device__ int g_he_cnt[N_HE];
__device__ int g_nd_off[N_NODES + 1];
__device__ int g_he_off[N_HE + 1];
__device__ int g_nd_hes[N_INC];
__device__ int g_he_nodes[N_INC];
__device__ int g_bsum[128];

__device__ float g_bnst[2 * HID];    // [0..255]=sum, [256..511]=sumsq

// ---------------- helpers ----------------
__device__ __forceinline__ uint32_t smem_to_u32(const void* p) {
    uint32_t a;
    asm("{ .reg .u64 t; cvta.to.shared.u64 t, %1; cvt.u32.u64 %0, t; }" : "=r"(a) : "l"(p));
    return a;
}
#define SWZ(off) ((off) ^ (((off) >> 3) & 0x70))

__device__ __forceinline__ void cp_async16(uint32_t dst, const void* src) {
    asm volatile("cp.async.cg.shared.global [%0], [%1], 16;" :: "r"(dst), "l"(src) : "memory");
}
__device__ __forceinline__ uint32_t pack_h2(float x, float y) {
    __half2 h = __floats2half2_rn(x, y);
    return *reinterpret_cast<uint32_t*>(&h);
}
__device__ __forceinline__ float2 unpack_h2(uint32_t u) {
    __half2 h = *reinterpret_cast<__half2*>(&u);
    return __half22float2(h);
}

// ---------------- CSR build ----------------
__global__ void k_hist(const int* __restrict__ node_idx, const int* __restrict__ he_idx) {
    int i = blockIdx.x * blockDim.x + threadIdx.x;
    if (i < N_INC) {
        atomicAdd(&g_nd_cnt[node_idx[i]], 1);
        atomicAdd(&g_he_cnt[he_idx[i]], 1);
    }
}

__global__ void k_blk_sum2(int nb_nd) {
    bool he = (int)blockIdx.x >= nb_nd;
    const int* cnt = he ? g_he_cnt : g_nd_cnt;
    int n = he ? N_HE : N_NODES;
    int bid = he ? blockIdx.x - nb_nd : blockIdx.x;
    int* bs = g_bsum + (he ? 64 : 0);
    int tid = threadIdx.x;
    int base = bid * 2048;
    int s = 0;
#pragma unroll
    for (int i = 0; i < 8; i++) {
        int idx = base + i * 256 + tid;
        if (idx < n) s += cnt[idx];
    }
#pragma unroll
    for (int o = 16; o > 0; o >>= 1) s += __shfl_xor_sync(0xFFFFFFFFu, s, o);
    __shared__ int ws[8];
    if ((tid & 31) == 0) ws[tid >> 5] = s;
    __syncthreads();
    if (tid == 0) {
        int t = 0;
#pragma unroll
        for (int w = 0; w < 8; w++) t += ws[w];
        bs[bid] = t;
    }
}
__global__ void k_bsum_scan2(int nb_nd, int nb_he) {
    bool he = blockIdx.x == 1;
    int nb = he ? nb_he : nb_nd;
    int* bs = g_bsum + (he ? 64 : 0);
    int* off = he ? g_he_off : g_nd_off;
    int n = he ? N_HE : N_NODES;
    int tid = threadIdx.x;
    int lane = tid & 31, w = tid >> 5;
    int v = (tid < nb) ? bs[tid] : 0;
    int x = v;
#pragma unroll
    for (int o = 1; o < 32; o <<= 1) {
        int t = __shfl_up_sync(0xFFFFFFFFu, x, o);
        if (lane >= o) x += t;
    }
    __shared__ int ws[32];
    if (lane == 31) ws[w] = x;
    __syncthreads();
    if (w == 0) {
        int y = ws[lane];
        int z = y;
#pragma unroll
        for (int o = 1; o < 32; o <<= 1) {
            int t = __shfl_up_sync(0xFFFFFFFFu, z, o);
            if (lane >= o) z += t;
        }
        ws[lane] = z - y;
    }
    __syncthreads();
    int excl = x - v + ws[w];
    if (tid < nb) bs[tid] = excl;
    if (tid == nb - 1) off[n] = excl + v;
}
__global__ void k_blk_scan2(int nb_nd) {
    bool he = (int)blockIdx.x >= nb_nd;
    const int* cnt = he ? g_he_cnt : g_nd_cnt;
    int n = he ? N_HE : N_NODES;
    int bid = he ? blockIdx.x - nb_nd : blockIdx.x;
    const int* bs = g_bsum + (he ? 64 : 0);
    int* off = he ? g_he_off : g_nd_off;
    int tid = threadIdx.x;
    int base = bid * 2048;
    int v[8];
    int s = 0;
#pragma unroll
    for (int i = 0; i < 8; i++) {
        int idx = base + tid * 8 + i;
        v[i] = (idx < n) ? cnt[idx] : 0;
        s += v[i];
    }
    int lane = tid & 31, w = tid >> 5;
    int x = s;
#pragma unroll
    for (int o = 1; o < 32; o <<= 1) {
        int t = __shfl_up_sync(0xFFFFFFFFu, x, o);
        if (lane >= o) x += t;
    }
    __shared__ int ws[8];
    __shared__ int wexcl[8];
    if (lane == 31) ws[w] = x;
    __syncthreads();
    if (tid < 8) {
        int t = 0;
        for (int j = 0; j < tid; j++) t += ws[j];
        wexcl[tid] = t;
    }
    __syncthreads();
    int run = bs[bid] + wexcl[w] + (x - s);
#pragma unroll
    for (int i = 0; i < 8; i++) {
        int idx = base + tid * 8 + i;
        if (idx < n) off[idx] = run;
        run += v[i];
    }
}

__global__ void k_scatter(const int* __restrict__ node_idx, const int* __restrict__ he_idx) {
    int i = blockIdx.x * blockDim.x + threadIdx.x;
    if (i < N_INC) {
        int n = node_idx[i], e = he_idx[i];
        int p = atomicAdd(&g_he_cnt[e], 1);
        g_he_nodes[g_he_off[e] + p] = n;
        int q = atomicAdd(&g_nd_cnt[n], 1);
        g_nd_hes[g_nd_off[n] + q] = e;
    }
}

// ---------------- fused weight split (all 3 weights, one launch) ----------------
__device__ __forceinline__ void split_one(const float* __restrict__ W, __half* __restrict__ Ws,
                                          int K, int N, int i) {
    int k = i / N, n = i - k * N;
    float v = W[i];
    __half h = __float2half_rn(v);
    __half l = __float2half_rn(v - __half2float(h));
    __half* O = Ws + (size_t)n * 2 * K;
    O[k] = h;
    O[K + k] = l;
}
__global__ void k_split_W_all(const float* __restrict__ W1, const float* __restrict__ W2,
                              const float* __restrict__ W3) {
    int i = blockIdx.x * blockDim.x + threadIdx.x;
    if (i < 32768)        split_one(W1, g_W1s, IN_CH, HID, i);
    else if (i < 98304)   split_one(W2, g_W2s, HID, HID, i - 32768);
    else if (i < 131072)  split_one(W3, g_W3s, HID, OUT_CH, i - 98304);
}

// ---------------- GEMM: C[M,N]fp16 = A[M,K]fp16 @ (Bh+Bl)[N,2K]fp16^T ----------------
// A exact fp16; B split [hi(K)|lo(K)] recovers full fp32 weight precision:
// C = A*Bh + A*Bl with fp32 accumulation. One A tile reused for both B halves.
// CTA tile 128 x N, warps 4(M) x NWN, warp tile 32x64, double-buffered cp.async.
template <int NWN>
__global__ void __launch_bounds__(NWN * 128, 1)
gemm_f16(const __half* __restrict__ A, const __half* __restrict__ Bw,
         __half* __restrict__ C, int M, int K)
{
    constexpr int N = NWN * 64;
    constexpr int NT = NWN * 128;
    constexpr uint32_t NB = (uint32_t)N * 128;
    constexpr uint32_t STAGE = 16384 + 2 * NB;
    extern __shared__ char smc[];
    const uint32_t tbase = smem_to_u32(smc);
    const int tid  = threadIdx.x;
    const int lane = tid & 31;
    const int wid  = tid >> 5;
    const int wm   = wid / NWN;
    const int wn   = wid % NWN;
    const int row0 = blockIdx.y * 128;
    const int K64  = K >> 6;
    const int Kt   = 2 * K;

    // fold BN-stat zeroing into the GEMM (block y==0 only; runs before the
    // downstream node_gather launch consumes it)
    if (blockIdx.y == 0 && tid < 2 * HID) g_bnst[tid] = 0.f;

    float acc[2][8][4];
#pragma unroll
    for (int i = 0; i < 2; i++)
#pragma unroll
        for (int j = 0; j < 8; j++)
#pragma unroll
            for (int k = 0; k < 4; k++) acc[i][j][k] = 0.f;

    uint32_t a_off[2], b_off[4];
#pragma unroll
    for (int mf = 0; mf < 2; mf++)
        a_off[mf] = (uint32_t)((wm * 32 + mf * 16 + (lane & 15)) * 128 + (lane >> 4) * 16);
#pragma unroll
    for (int nf4 = 0; nf4 < 4; nf4++)
        b_off[nf4] = (uint32_t)((wn * 64 + nf4 * 16 + (lane & 7) + ((lane >> 4) & 1) * 8) * 128
                                + ((lane >> 3) & 1) * 16);

    auto load_chunk = [&](int c, int buf) {
        const __half* Ag = A + (size_t)row0 * K + c * 64;
        uint32_t ab = tbase + buf * STAGE;
        for (int i = tid; i < 1024; i += NT) {
            int r = i >> 3, q = i & 7;
            cp_async16(ab + SWZ((uint32_t)(r * 128 + q * 16)),
                       Ag + (size_t)r * K + q * 8);
        }
        uint32_t bb = tbase + buf * STAGE + 16384;
#pragma unroll
        for (int t = 0; t < 2; t++) {
            const __half* Bg = Bw + (size_t)(c + t * K64) * 64;
            for (int i = tid; i < N * 8; i += NT) {
                int r = i >> 3, q = i & 7;
                cp_async16(bb + t * NB + SWZ((uint32_t)(r * 128 + q * 16)),
                           Bg + (size_t)r * Kt + q * 8);
            }
        }
        asm volatile("cp.async.commit_group;" ::: "memory");
    };

    load_chunk(0, 0);

    for (int c = 0; c < K64; c++) {
        int buf = c & 1;
        if (c + 1 < K64) {
            load_chunk(c + 1, buf ^ 1);
            asm volatile("cp.async.wait_group 1;" ::: "memory");
        } else {
            asm volatile("cp.async.wait_group 0;" ::: "memory");
        }
        __syncthreads();

        uint32_t ab = tbase + buf * STAGE;
        uint32_t bb = tbase + buf * STAGE + 16384;
#pragma unroll
        for (int k16 = 0; k16 < 4; k16++) {
            uint32_t a[2][4];
#pragma unroll
            for (int mf = 0; mf < 2; mf++) {
                uint32_t addr = ab + SWZ(a_off[mf] + (uint32_t)(k16 * 32));
                asm volatile("ldmatrix.sync.aligned.m8n8.x4.shared.b16 {%0,%1,%2,%3}, [%4];"
                             : "=r"(a[mf][0]), "=r"(a[mf][1]), "=r"(a[mf][2]), "=r"(a[mf][3])
                             : "r"(addr));
            }
#pragma unroll
            for (int t = 0; t < 2; t++) {
                uint32_t b[4][4];
#pragma unroll
                for (int nf4 = 0; nf4 < 4; nf4++) {
                    uint32_t addr = bb + t * NB + SWZ(b_off[nf4] + (uint32_t)(k16 * 32));
                    asm volatile("ldmatrix.sync.aligned.m8n8.x4.shared.b16 {%0,%1,%2,%3}, [%4];"
                                 : "=r"(b[nf4][0]), "=r"(b[nf4][1]), "=r"(b[nf4][2]), "=r"(b[nf4][3])
                                 : "r"(addr));
                }
#pragma unroll
                for (int mf = 0; mf < 2; mf++)
#pragma unroll
                    for (int nf = 0; nf < 8; nf++) {
                        asm volatile(
                            "mma.sync.aligned.m16n8k16.row.col.f32.f16.f16.f32 "
                            "{%0,%1,%2,%3}, {%4,%5,%6,%7}, {%8,%9}, {%0,%1,%2,%3};"
                            : "+f"(acc[mf][nf][0]), "+f"(acc[mf][nf][1]),
                              "+f"(acc[mf][nf][2]), "+f"(acc[mf][nf][3])
                            : "r"(a[mf][0]), "r"(a[mf][1]), "r"(a[mf][2]), "r"(a[mf][3]),
                              "r"(b[nf >> 1][(nf & 1) * 2]), "r"(b[nf >> 1][(nf & 1) * 2 + 1]));
                    }
            }
        }
        __syncthreads();
    }

#pragma unroll
    for (int mf = 0; mf < 2; mf++) {
        int r0g = row0 + wm * 32 + mf * 16 + (lane >> 2);
        int r1g = r0g + 8;
#pragma unroll
        for (int nf = 0; nf < 8; nf++) {
            int col = wn * 64 + nf * 8 + (lane & 3) * 2;
            uint32_t v0 = pack_h2(acc[mf][nf][0], acc[mf][nf][1]);
            uint32_t v1 = pack_h2(acc[mf][nf][2], acc[mf][nf][3]);
            if (r0g < M) *reinterpret_cast<uint32_t*>(C + (size_t)r0g * N + col) = v0;
            if (r1g < M) *reinterpret_cast<uint32_t*>(C + (size_t)r1g * N + col) = v1;
        }
    }
}

// ---------------- aggregation ----------------
// layer-1 hyperedge gather: x fp32 [N_NODES,128] -> HE fp16 [N_HE,128]
__global__ void __launch_bounds__(256) k_he_gather128(const float* __restrict__ X,
                                                      __half* __restrict__ HE) {
    int tid = threadIdx.x;
    int f4 = tid & 31;
    int sub = tid >> 5;              // 0..7
    int base = blockIdx.x * 32;
#pragma unroll
    for (int i = 0; i < 4; i++) {
        int e = base + i * 8 + sub;
        if (e >= N_HE) break;
        int s = g_he_off[e], t = g_he_off[e + 1];
        float4 acc = make_float4(0.f, 0.f, 0.f, 0.f);
        for (int j = s; j < t; j++) {
            int n = g_he_nodes[j];
            float4 v = reinterpret_cast<const float4*>(X)[(size_t)n * 32 + f4];
            acc.x += v.x; acc.y += v.y; acc.z += v.z; acc.w += v.w;
        }
        float4 o = make_float4(0.f, 0.f, 0.f, 0.f);
        if (t > s) {
            float inv = 1.0f / (float)(t - s);
            o.x = acc.x * inv; o.y = acc.y * inv; o.z = acc.z * inv; o.w = acc.w * inv;
        }
        reinterpret_cast<uint2*>(HE)[(size_t)e * 32 + f4] =
            make_uint2(pack_h2(o.x, o.y), pack_h2(o.z, o.w));
    }
}

// hyperedge gather F=256 + BN affine fused: X1 fp16 -> HE fp16
__global__ void __launch_bounds__(256) k_he_gather_bn(const __half* __restrict__ X,
                                                      __half* __restrict__ HE,
                                                      const float* __restrict__ gam,
                                                      const float* __restrict__ bet) {
    int tid = threadIdx.x;
    int f4 = tid & 63;
    int sub = tid >> 6;              // 0..3
    int c = f4 * 4;
    const float invN = 1.0f / (float)N_NODES;
    float sc[4], sh[4];
#pragma unroll
    for (int u = 0; u < 4; u++) {
        float m = g_bnst[c + u] * invN;
        float var = g_bnst[HID + c + u] * invN - m * m;
        float s = gam[c + u] * rsqrtf(var + BN_EPS);
        sc[u] = s;
        sh[u] = bet[c + u] - m * s;
    }
    int base = blockIdx.x * 16;
#pragma unroll
    for (int i = 0; i < 4; i++) {
        int e = base + i * 4 + sub;
        if (e >= N_HE) break;
        int s = g_he_off[e], t = g_he_off[e + 1];
        float4 acc = make_float4(0.f, 0.f, 0.f, 0.f);
        for (int j = s; j < t; j++) {
            int n = g_he_nodes[j];
            uint2 u2 = reinterpret_cast<const uint2*>(X)[(size_t)n * 64 + f4];
            float2 v0 = unpack_h2(u2.x);
            float2 v1 = unpack_h2(u2.y);
            acc.x += v0.x; acc.y += v0.y; acc.z += v1.x; acc.w += v1.y;
        }
        float4 o = make_float4(0.f, 0.f, 0.f, 0.f);
        if (t > s) {
            float inv = 1.0f / (float)(t - s);
            o.x = (acc.x * inv) * sc[0] + sh[0];
            o.y = (acc.y * inv) * sc[1] + sh[1];
            o.z = (acc.z * inv) * sc[2] + sh[2];
            o.w = (acc.w * inv) * sc[3] + sh[3];
        }
        reinterpret_cast<uint2*>(HE)[(size_t)e * 64 + f4] =
            make_uint2(pack_h2(o.x, o.y), pack_h2(o.z, o.w));
    }
}

// node gather F=256 + bias + relu + fused BN-stats: HEW fp16 -> X1 fp16
__global__ void __launch_bounds__(256) k_node_gather_bn(const __half* __restrict__ HEW,
                                                        const float* __restrict__ bias,
                                                        __half* __restrict__ OUT) {
    __shared__ float rs[4][HID];
    __shared__ float rq[4][HID];
    int tid = threadIdx.x;
    int f4 = tid & 63;
    int sub = tid >> 6;              // 0..3
    int c = f4 * 4;
    float4 b4 = reinterpret_cast<const float4*>(bias)[f4];
    float s4[4] = {0.f, 0.f, 0.f, 0.f};
    float q4[4] = {0.f, 0.f, 0.f, 0.f};
    int base = blockIdx.x * 128;
#pragma unroll 4
    for (int i = 0; i < 32; i++) {
        int n = base + i * 4 + sub;
        if (n >= N_NODES) break;
        int s = g_nd_off[n], t = g_nd_off[n + 1];
        float4 acc = make_float4(0.f, 0.f, 0.f, 0.f);
        for (int j = s; j < t; j++) {
            int e = g_nd_hes[j];
            uint2 u2 = reinterpret_cast<const uint2*>(HEW)[(size_t)e * 64 + f4];
            float2 v0 = unpack_h2(u2.x);
            float2 v1 = unpack_h2(u2.y);
            acc.x += v0.x; acc.y += v0.y; acc.z += v1.x; acc.w += v1.y;
        }
        float inv = (t > s) ? 1.0f / (float)(t - s) : 0.f;
        float4 o;
        o.x = fmaxf(fmaf(acc.x, inv, b4.x), 0.f);
        o.y = fmaxf(fmaf(acc.y, inv, b4.y), 0.f);
        o.z = fmaxf(fmaf(acc.z, inv, b4.z), 0.f);
        o.w = fmaxf(fmaf(acc.w, inv, b4.w), 0.f);
        reinterpret_cast<uint2*>(OUT)[(size_t)n * 64 + f4] =
            make_uint2(pack_h2(o.x, o.y), pack_h2(o.z, o.w));
        s4[0] += o.x; s4[1] += o.y; s4[2] += o.z; s4[3] += o.w;
        q4[0] += o.x * o.x; q4[1] += o.y * o.y; q4[2] += o.z * o.z; q4[3] += o.w * o.w;
    }
#pragma unroll
    for (int u = 0; u < 4; u++) {
        rs[sub][c + u] = s4[u];
        rq[sub][c + u] = q4[u];
    }
    __syncthreads();
    if (sub == 0) {
#pragma unroll
        for (int u = 0; u < 4; u++) {
            float ts = rs[0][c + u] + rs[1][c + u] + rs[2][c + u] + rs[3][c + u];
            float tq = rq[0][c + u] + rq[1][c + u] + rq[2][c + u] + rq[3][c + u];
            atomicAdd(&g_bnst[c + u], ts);
            atomicAdd(&g_bnst[HID + c + u], tq);
        }
    }
}

// node gather F=128 + bias + relu -> out fp32 (layer 3)
__global__ void __launch_bounds__(256) k_node_gather128(const __half* __restrict__ HEW,
                                                        const float* __restrict__ bias,
                                                        float* __restrict__ OUT) {
    int tid = threadIdx.x;
    int f4 = tid & 31;
    int sub = tid >> 5;              // 0..7
    float4 b4 = reinterpret_cast<const float4*>(bias)[f4];
    int base = blockIdx.x * 128;
#pragma unroll 4
    for (int i = 0; i < 16; i++) {
        int n = base + i * 8 + sub;
        if (n >= N_NODES) break;
        int s = g_nd_off[n], t = g_nd_off[n + 1];
        float4 acc = make_float4(0.f, 0.f, 0.f, 0.f);
        for (int j = s; j < t; j++) {
            int e = g_nd_hes[j];
            uint2 u2 = reinterpret_cast<const uint2*>(HEW)[(size_t)e * 32 + f4];
            float2 v0 = unpack_h2(u2.x);
            float2 v1 = unpack_h2(u2.y);
            acc.x += v0.x; acc.y += v0.y; acc.z += v1.x; acc.w += v1.y;
        }
        float inv = (t > s) ? 1.0f / (float)(t - s) : 0.f;
        float4 o;
        o.x = fmaxf(fmaf(acc.x, inv, b4.x), 0.f);
        o.y = fmaxf(fmaf(acc.y, inv, b4.y), 0.f);
        o.z = fmaxf(fmaf(acc.z, inv, b4.z), 0.f);
        o.w = fmaxf(fmaf(acc.w, inv, b4.w), 0.f);
        reinterpret_cast<float4*>(OUT)[(size_t)n * 32 + f4] = o;
    }
}

// ---------------- launch ----------------
extern "C" void kernel_launch(void* const* d_in, const int* in_sizes, int n_in,
                              void* d_out, int out_size) {
    const float* x    = (const float*)d_in[0];
    const int*   edge = (const int*)d_in[1];
    const int*   node_idx = edge;
    const int*   he_idx   = edge + N_INC;
    const float* W1 = (const float*)d_in[2];
    const float* b1 = (const float*)d_in[3];
    const float* g1 = (const float*)d_in[4];
    const float* be1 = (const float*)d_in[5];
    const float* W2 = (const float*)d_in[6];
    const float* b2 = (const float*)d_in[7];
    const float* g2 = (const float*)d_in[8];
    const float* be2 = (const float*)d_in[9];
    const float* W3 = (const float*)d_in[10];
    const float* b3 = (const float*)d_in[11];
    float* out = (float*)d_out;

    void *p_X1, *p_HE, *p_HEW, *p_W1s, *p_W2s, *p_W3s, *p_nd_cnt, *p_he_cnt;
    cudaGetSymbolAddress(&p_X1, g_X1);
    cudaGetSymbolAddress(&p_HE, g_HE);
    cudaGetSymbolAddress(&p_HEW, g_HEW);
    cudaGetSymbolAddress(&p_W1s, g_W1s);
    cudaGetSymbolAddress(&p_W2s, g_W2s);
    cudaGetSymbolAddress(&p_W3s, g_W3s);
    cudaGetSymbolAddress(&p_nd_cnt, g_nd_cnt);
    cudaGetSymbolAddress(&p_he_cnt, g_he_cnt);
    __half* X1  = (__half*)p_X1;
    __half* HE  = (__half*)p_HE;
    __half* HEW = (__half*)p_HEW;
    __half* W1s = (__half*)p_W1s;
    __half* W2s = (__half*)p_W2s;
    __half* W3s = (__half*)p_W3s;

    const int GEMM_SMEM_N256 = 2 * (16384 + 2 * 256 * 128);   // 163840
    const int GEMM_SMEM_N128 = 2 * (16384 + 2 * 128 * 128);   // 98304
    cudaFuncSetAttribute(gemm_f16<4>, cudaFuncAttributeMaxDynamicSharedMemorySize, GEMM_SMEM_N256);
    cudaFuncSetAttribute(gemm_f16<2>, cudaFuncAttributeMaxDynamicSharedMemorySize, GEMM_SMEM_N128);
    const int he_tiles = (N_HE + 127) / 128;      // 235
    const int he_g128 = (N_HE + 31) / 32;         // 938
    const int he_g256 = (N_HE + 15) / 16;         // 1875
    const int nd_g = (N_NODES + 127) / 128;       // 782

    // ---- weight splits (fused) ----
    k_split_W_all<<<512, 256>>>(W1, W2, W3);

    // ---- CSR build ----
    cudaMemsetAsync(p_nd_cnt, 0, N_NODES * sizeof(int));
    cudaMemsetAsync(p_he_cnt, 0, N_HE * sizeof(int));
    k_hist<<<(N_INC + 255) / 256, 256>>>(node_idx, he_idx);
    const int nb_nd = (N_NODES + 2047) / 2048;
    const int nb_he = (N_HE + 2047) / 2048;
    k_blk_sum2<<<nb_nd + nb_he, 256>>>(nb_nd);
    k_bsum_scan2<<<2, 1024>>>(nb_nd, nb_he);
    k_blk_scan2<<<nb_nd + nb_he, 256>>>(nb_nd);
    cudaMemsetAsync(p_nd_cnt, 0, N_NODES * sizeof(int));
    cudaMemsetAsync(p_he_cnt, 0, N_HE * sizeof(int));
    k_scatter<<<(N_INC + 255) / 256, 256>>>(node_idx, he_idx);

    // ---- layer 1: he_gather(x) -> GEMM -> node_gather+bn_stats ----
    {
        k_he_gather128<<<he_g128, 256>>>(x, HE);
        dim3 grid(1, he_tiles);
        gemm_f16<4><<<grid, 512, GEMM_SMEM_N256>>>(HE, W1s, HEW, N_HE, IN_CH);
        k_node_gather_bn<<<nd_g, 256>>>(HEW, b1, X1);
    }
    // ---- layer 2: he_gather(BN1 fused) -> GEMM -> node_gather+bn_stats ----
    {
        k_he_gather_bn<<<he_g256, 256>>>(X1, HE, g1, be1);
        dim3 grid(1, he_tiles);
        gemm_f16<4><<<grid, 512, GEMM_SMEM_N256>>>(HE, W2s, HEW, N_HE, HID);
        k_node_gather_bn<<<nd_g, 256>>>(HEW, b2, X1);
    }
    // ---- layer 3: he_gather(BN2 fused) -> GEMM(N=128) -> node_gather -> out ----
    {
        k_he_gather_bn<<<he_g256, 256>>>(X1, HE, g2, be2);
        dim3 grid(1, he_tiles);
        gemm_f16<2><<<grid, 256, GEMM_SMEM_N128>>>(HE, W3s, HEW, N_HE, HID);
        k_node_gather128<<<nd_g, 256>>>(HEW, b3, out);
    }
}

// round 15
// speedup vs baseline: 2.1148x; 1.0144x over previous
#include <cuda_runtime.h>
#include <cuda_bf16.h>
#include <cuda_fp16.h>
#include <cstdint>

#define N_NODES 100000
#define N_HE    30000
#define N_INC   300000
#define IN_CH   128
#define HID     256
#define OUT_CH  128
#define BN_EPS  1e-5f

// ---------------- device scratch (allocation-free, zero-initialized) ----------------
__device__ __half g_X1[(size_t)N_NODES * HID];          // node features fp16
__device__ __half g_HE[(size_t)(N_HE + 128) * HID];     // hyperedge features fp16 (padded)
__device__ __half g_HEW[(size_t)N_HE * HID];            // hyperedge features after GEMM fp16
__device__ __half g_W1s[(size_t)HID * 2 * IN_CH];       // [256, 256] = [hi(128)|lo(128)]
__device__ __half g_W2s[(size_t)HID * 2 * HID];         // [256, 512]
__device__ __half g_W3s[(size_t)OUT_CH * 2 * HID];      // [128, 512]

__device__ int g_nd_cnt[N_NODES];
__device__ int g_he_cnt[N_HE];
__device__ int g_nd_off[N_NODES + 1];
__device__ int g_he_off[N_HE + 1];
__device__ int g_nd_hes[N_INC];
__device__ int g_he_nodes[N_INC];
__device__ int g_bsum[128];

__device__ float g_bnst[2 * HID];    // [0..255]=sum, [256..511]=sumsq

// ---------------- helpers ----------------
__device__ __forceinline__ uint32_t smem_to_u32(const void* p) {
    uint32_t a;
    asm("{ .reg .u64 t; cvta.to.shared.u64 t, %1; cvt.u32.u64 %0, t; }" : "=r"(a) : "l"(p));
    return a;
}
#define SWZ(off) ((off) ^ (((off) >> 3) & 0x70))

__device__ __forceinline__ void cp_async16(uint32_t dst, const void* src) {
    asm volatile("cp.async.cg.shared.global [%0], [%1], 16;" :: "r"(dst), "l"(src) : "memory");
}
__device__ __forceinline__ uint32_t pack_h2(float x, float y) {
    __half2 h = __floats2half2_rn(x, y);
    return *reinterpret_cast<uint32_t*>(&h);
}
__device__ __forceinline__ float2 unpack_h2(uint32_t u) {
    __half2 h = *reinterpret_cast<__half2*>(&u);
    return __half22float2(h);
}
__device__ __forceinline__ void acc_h2(float4& acc, uint2 u2) {
    float2 v0 = unpack_h2(u2.x);
    float2 v1 = unpack_h2(u2.y);
    acc.x += v0.x; acc.y += v0.y; acc.z += v1.x; acc.w += v1.y;
}

// ---------------- CSR build ----------------
__global__ void k_hist(const int* __restrict__ node_idx, const int* __restrict__ he_idx) {
    int i = blockIdx.x * blockDim.x + threadIdx.x;
    if (i < N_INC) {
        atomicAdd(&g_nd_cnt[node_idx[i]], 1);
        atomicAdd(&g_he_cnt[he_idx[i]], 1);
    }
}

__global__ void k_blk_sum2(int nb_nd) {
    bool he = (int)blockIdx.x >= nb_nd;
    const int* cnt = he ? g_he_cnt : g_nd_cnt;
    int n = he ? N_HE : N_NODES;
    int bid = he ? blockIdx.x - nb_nd : blockIdx.x;
    int* bs = g_bsum + (he ? 64 : 0);
    int tid = threadIdx.x;
    int base = bid * 2048;
    int s = 0;
#pragma unroll
    for (int i = 0; i < 8; i++) {
        int idx = base + i * 256 + tid;
        if (idx < n) s += cnt[idx];
    }
#pragma unroll
    for (int o = 16; o > 0; o >>= 1) s += __shfl_xor_sync(0xFFFFFFFFu, s, o);
    __shared__ int ws[8];
    if ((tid & 31) == 0) ws[tid >> 5] = s;
    __syncthreads();
    if (tid == 0) {
        int t = 0;
#pragma unroll
        for (int w = 0; w < 8; w++) t += ws[w];
        bs[bid] = t;
    }
}
__global__ void k_bsum_scan2(int nb_nd, int nb_he) {
    bool he = blockIdx.x == 1;
    int nb = he ? nb_he : nb_nd;
    int* bs = g_bsum + (he ? 64 : 0);
    int* off = he ? g_he_off : g_nd_off;
    int n = he ? N_HE : N_NODES;
    int tid = threadIdx.x;
    int lane = tid & 31, w = tid >> 5;
    int v = (tid < nb) ? bs[tid] : 0;
    int x = v;
#pragma unroll
    for (int o = 1; o < 32; o <<= 1) {
        int t = __shfl_up_sync(0xFFFFFFFFu, x, o);
        if (lane >= o) x += t;
    }
    __shared__ int ws[32];
    if (lane == 31) ws[w] = x;
    __syncthreads();
    if (w == 0) {
        int y = ws[lane];
        int z = y;
#pragma unroll
        for (int o = 1; o < 32; o <<= 1) {
            int t = __shfl_up_sync(0xFFFFFFFFu, z, o);
            if (lane >= o) z += t;
        }
        ws[lane] = z - y;
    }
    __syncthreads();
    int excl = x - v + ws[w];
    if (tid < nb) bs[tid] = excl;
    if (tid == nb - 1) off[n] = excl + v;
}
// per-block scan with base; also re-zeroes cnt for the scatter pass
__global__ void k_blk_scan2(int nb_nd) {
    bool he = (int)blockIdx.x >= nb_nd;
    int* cnt = he ? g_he_cnt : g_nd_cnt;
    int n = he ? N_HE : N_NODES;
    int bid = he ? blockIdx.x - nb_nd : blockIdx.x;
    const int* bs = g_bsum + (he ? 64 : 0);
    int* off = he ? g_he_off : g_nd_off;
    int tid = threadIdx.x;
    int base = bid * 2048;
    int v[8];
    int s = 0;
#pragma unroll
    for (int i = 0; i < 8; i++) {
        int idx = base + tid * 8 + i;
        v[i] = (idx < n) ? cnt[idx] : 0;
        s += v[i];
    }
    int lane = tid & 31, w = tid >> 5;
    int x = s;
#pragma unroll
    for (int o = 1; o < 32; o <<= 1) {
        int t = __shfl_up_sync(0xFFFFFFFFu, x, o);
        if (lane >= o) x += t;
    }
    __shared__ int ws[8];
    __shared__ int wexcl[8];
    if (lane == 31) ws[w] = x;
    __syncthreads();
    if (tid < 8) {
        int t = 0;
        for (int j = 0; j < tid; j++) t += ws[j];
        wexcl[tid] = t;
    }
    __syncthreads();
    int run = bs[bid] + wexcl[w] + (x - s);
#pragma unroll
    for (int i = 0; i < 8; i++) {
        int idx = base + tid * 8 + i;
        if (idx < n) {
            off[idx] = run;
            cnt[idx] = 0;          // re-zero for scatter
        }
        run += v[i];
    }
}

__global__ void k_scatter(const int* __restrict__ node_idx, const int* __restrict__ he_idx) {
    int i = blockIdx.x * blockDim.x + threadIdx.x;
    if (i < N_INC) {
        int n = node_idx[i], e = he_idx[i];
        int p = atomicAdd(&g_he_cnt[e], 1);
        g_he_nodes[g_he_off[e] + p] = n;
        int q = atomicAdd(&g_nd_cnt[n], 1);
        g_nd_hes[g_nd_off[n] + q] = e;
    }
}

// ---------------- fused weight split + cnt zeroing (one launch) ----------------
__device__ __forceinline__ void split_one(const float* __restrict__ W, __half* __restrict__ Ws,
                                          int K, int N, int i) {
    int k = i / N, n = i - k * N;
    float v = W[i];
    __half h = __float2half_rn(v);
    __half l = __float2half_rn(v - __half2float(h));
    __half* O = Ws + (size_t)n * 2 * K;
    O[k] = h;
    O[K + k] = l;
}
__global__ void k_split_W_all(const float* __restrict__ W1, const float* __restrict__ W2,
                              const float* __restrict__ W3) {
    int i = blockIdx.x * blockDim.x + threadIdx.x;
    if (i < 32768)        split_one(W1, g_W1s, IN_CH, HID, i);
    else if (i < 98304)   split_one(W2, g_W2s, HID, HID, i - 32768);
    else if (i < 131072)  split_one(W3, g_W3s, HID, OUT_CH, i - 98304);
    // fold initial cnt zeroing (130000 ints <= 131072 threads)
    if (i < N_NODES) g_nd_cnt[i] = 0;
    else if (i < N_NODES + N_HE) g_he_cnt[i - N_NODES] = 0;
}

// ---------------- GEMM: C[M,N]fp16 = A[M,K]fp16 @ (Bh+Bl)[N,2K]fp16^T ----------------
template <int NWN>
__global__ void __launch_bounds__(NWN * 128, 1)
gemm_f16(const __half* __restrict__ A, const __half* __restrict__ Bw,
         __half* __restrict__ C, int M, int K)
{
    constexpr int N = NWN * 64;
    constexpr int NT = NWN * 128;
    constexpr uint32_t NB = (uint32_t)N * 128;
    constexpr uint32_t STAGE = 16384 + 2 * NB;
    extern __shared__ char smc[];
    const uint32_t tbase = smem_to_u32(smc);
    const int tid  = threadIdx.x;
    const int lane = tid & 31;
    const int wid  = tid >> 5;
    const int wm   = wid / NWN;
    const int wn   = wid % NWN;
    const int row0 = blockIdx.y * 128;
    const int K64  = K >> 6;
    const int Kt   = 2 * K;

    if (blockIdx.y == 0 && tid < 2 * HID) g_bnst[tid] = 0.f;

    float acc[2][8][4];
#pragma unroll
    for (int i = 0; i < 2; i++)
#pragma unroll
        for (int j = 0; j < 8; j++)
#pragma unroll
            for (int k = 0; k < 4; k++) acc[i][j][k] = 0.f;

    uint32_t a_off[2], b_off[4];
#pragma unroll
    for (int mf = 0; mf < 2; mf++)
        a_off[mf] = (uint32_t)((wm * 32 + mf * 16 + (lane & 15)) * 128 + (lane >> 4) * 16);
#pragma unroll
    for (int nf4 = 0; nf4 < 4; nf4++)
        b_off[nf4] = (uint32_t)((wn * 64 + nf4 * 16 + (lane & 7) + ((lane >> 4) & 1) * 8) * 128
                                + ((lane >> 3) & 1) * 16);

    auto load_chunk = [&](int c, int buf) {
        const __half* Ag = A + (size_t)row0 * K + c * 64;
        uint32_t ab = tbase + buf * STAGE;
        for (int i = tid; i < 1024; i += NT) {
            int r = i >> 3, q = i & 7;
            cp_async16(ab + SWZ((uint32_t)(r * 128 + q * 16)),
                       Ag + (size_t)r * K + q * 8);
        }
        uint32_t bb = tbase + buf * STAGE + 16384;
#pragma unroll
        for (int t = 0; t < 2; t++) {
            const __half* Bg = Bw + (size_t)(c + t * K64) * 64;
            for (int i = tid; i < N * 8; i += NT) {
                int r = i >> 3, q = i & 7;
                cp_async16(bb + t * NB + SWZ((uint32_t)(r * 128 + q * 16)),
                           Bg + (size_t)r * Kt + q * 8);
            }
        }
        asm volatile("cp.async.commit_group;" ::: "memory");
    };

    load_chunk(0, 0);

    for (int c = 0; c < K64; c++) {
        int buf = c & 1;
        if (c + 1 < K64) {
            load_chunk(c + 1, buf ^ 1);
            asm volatile("cp.async.wait_group 1;" ::: "memory");
        } else {
            asm volatile("cp.async.wait_group 0;" ::: "memory");
        }
        __syncthreads();

        uint32_t ab = tbase + buf * STAGE;
        uint32_t bb = tbase + buf * STAGE + 16384;
#pragma unroll
        for (int k16 = 0; k16 < 4; k16++) {
            uint32_t a[2][4];
#pragma unroll
            for (int mf = 0; mf < 2; mf++) {
                uint32_t addr = ab + SWZ(a_off[mf] + (uint32_t)(k16 * 32));
                asm volatile("ldmatrix.sync.aligned.m8n8.x4.shared.b16 {%0,%1,%2,%3}, [%4];"
                             : "=r"(a[mf][0]), "=r"(a[mf][1]), "=r"(a[mf][2]), "=r"(a[mf][3])
                             : "r"(addr));
            }
#pragma unroll
            for (int t = 0; t < 2; t++) {
                uint32_t b[4][4];
#pragma unroll
                for (int nf4 = 0; nf4 < 4; nf4++) {
                    uint32_t addr = bb + t * NB + SWZ(b_off[nf4] + (uint32_t)(k16 * 32));
                    asm volatile("ldmatrix.sync.aligned.m8n8.x4.shared.b16 {%0,%1,%2,%3}, [%4];"
                                 : "=r"(b[nf4][0]), "=r"(b[nf4][1]), "=r"(b[nf4][2]), "=r"(b[nf4][3])
                                 : "r"(addr));
                }
#pragma unroll
                for (int mf = 0; mf < 2; mf++)
#pragma unroll
                    for (int nf = 0; nf < 8; nf++) {
                        asm volatile(
                            "mma.sync.aligned.m16n8k16.row.col.f32.f16.f16.f32 "
                            "{%0,%1,%2,%3}, {%4,%5,%6,%7}, {%8,%9}, {%0,%1,%2,%3};"
                            : "+f"(acc[mf][nf][0]), "+f"(acc[mf][nf][1]),
                              "+f"(acc[mf][nf][2]), "+f"(acc[mf][nf][3])
                            : "r"(a[mf][0]), "r"(a[mf][1]), "r"(a[mf][2]), "r"(a[mf][3]),
                              "r"(b[nf >> 1][(nf & 1) * 2]), "r"(b[nf >> 1][(nf & 1) * 2 + 1]));
                    }
            }
        }
        __syncthreads();
    }

#pragma unroll
    for (int mf = 0; mf < 2; mf++) {
        int r0g = row0 + wm * 32 + mf * 16 + (lane >> 2);
        int r1g = r0g + 8;
#pragma unroll
        for (int nf = 0; nf < 8; nf++) {
            int col = wn * 64 + nf * 8 + (lane & 3) * 2;
            uint32_t v0 = pack_h2(acc[mf][nf][0], acc[mf][nf][1]);
            uint32_t v1 = pack_h2(acc[mf][nf][2], acc[mf][nf][3]);
            if (r0g < M) *reinterpret_cast<uint32_t*>(C + (size_t)r0g * N + col) = v0;
            if (r1g < M) *reinterpret_cast<uint32_t*>(C + (size_t)r1g * N + col) = v1;
        }
    }
}

// ---------------- aggregation (all inner loops 4x unrolled for MLP) ----------------
// layer-1 hyperedge gather: x fp32 [N_NODES,128] -> HE fp16 [N_HE,128]
__global__ void __launch_bounds__(256) k_he_gather128(const float* __restrict__ X,
                                                      __half* __restrict__ HE) {
    int tid = threadIdx.x;
    int f4 = tid & 31;
    int sub = tid >> 5;              // 0..7
    int base = blockIdx.x * 32;
#pragma unroll
    for (int i = 0; i < 4; i++) {
        int e = base + i * 8 + sub;
        if (e >= N_HE) break;
        int s = g_he_off[e], t = g_he_off[e + 1];
        float4 acc = make_float4(0.f, 0.f, 0.f, 0.f);
        int j = s;
        for (; j + 4 <= t; j += 4) {
            int n0 = g_he_nodes[j], n1 = g_he_nodes[j + 1];
            int n2 = g_he_nodes[j + 2], n3 = g_he_nodes[j + 3];
            float4 v0 = reinterpret_cast<const float4*>(X)[(size_t)n0 * 32 + f4];
            float4 v1 = reinterpret_cast<const float4*>(X)[(size_t)n1 * 32 + f4];
            float4 v2 = reinterpret_cast<const float4*>(X)[(size_t)n2 * 32 + f4];
            float4 v3 = reinterpret_cast<const float4*>(X)[(size_t)n3 * 32 + f4];
            acc.x += v0.x + v1.x + v2.x + v3.x;
            acc.y += v0.y + v1.y + v2.y + v3.y;
            acc.z += v0.z + v1.z + v2.z + v3.z;
            acc.w += v0.w + v1.w + v2.w + v3.w;
        }
        for (; j < t; j++) {
            int n = g_he_nodes[j];
            float4 v = reinterpret_cast<const float4*>(X)[(size_t)n * 32 + f4];
            acc.x += v.x; acc.y += v.y; acc.z += v.z; acc.w += v.w;
        }
        float4 o = make_float4(0.f, 0.f, 0.f, 0.f);
        if (t > s) {
            float inv = 1.0f / (float)(t - s);
            o.x = acc.x * inv; o.y = acc.y * inv; o.z = acc.z * inv; o.w = acc.w * inv;
        }
        reinterpret_cast<uint2*>(HE)[(size_t)e * 32 + f4] =
            make_uint2(pack_h2(o.x, o.y), pack_h2(o.z, o.w));
    }
}

// hyperedge gather F=256 + BN affine fused: X1 fp16 -> HE fp16
__global__ void __launch_bounds__(256) k_he_gather_bn(const __half* __restrict__ X,
                                                      __half* __restrict__ HE,
                                                      const float* __restrict__ gam,
                                                      const float* __restrict__ bet) {
    int tid = threadIdx.x;
    int f4 = tid & 63;
    int sub = tid >> 6;              // 0..3
    int c = f4 * 4;
    const float invN = 1.0f / (float)N_NODES;
    float sc[4], sh[4];
#pragma unroll
    for (int u = 0; u < 4; u++) {
        float m = g_bnst[c + u] * invN;
        float var = g_bnst[HID + c + u] * invN - m * m;
        float s = gam[c + u] * rsqrtf(var + BN_EPS);
        sc[u] = s;
        sh[u] = bet[c + u] - m * s;
    }
    int base = blockIdx.x * 16;
#pragma unroll
    for (int i = 0; i < 4; i++) {
        int e = base + i * 4 + sub;
        if (e >= N_HE) break;
        int s = g_he_off[e], t = g_he_off[e + 1];
        float4 acc = make_float4(0.f, 0.f, 0.f, 0.f);
        int j = s;
        for (; j + 4 <= t; j += 4) {
            int n0 = g_he_nodes[j], n1 = g_he_nodes[j + 1];
            int n2 = g_he_nodes[j + 2], n3 = g_he_nodes[j + 3];
            uint2 u0 = reinterpret_cast<const uint2*>(X)[(size_t)n0 * 64 + f4];
            uint2 u1 = reinterpret_cast<const uint2*>(X)[(size_t)n1 * 64 + f4];
            uint2 u2 = reinterpret_cast<const uint2*>(X)[(size_t)n2 * 64 + f4];
            uint2 u3 = reinterpret_cast<const uint2*>(X)[(size_t)n3 * 64 + f4];
            acc_h2(acc, u0); acc_h2(acc, u1); acc_h2(acc, u2); acc_h2(acc, u3);
        }
        for (; j < t; j++) {
            int n = g_he_nodes[j];
            acc_h2(acc, reinterpret_cast<const uint2*>(X)[(size_t)n * 64 + f4]);
        }
        float4 o = make_float4(0.f, 0.f, 0.f, 0.f);
        if (t > s) {
            float inv = 1.0f / (float)(t - s);
            o.x = (acc.x * inv) * sc[0] + sh[0];
            o.y = (acc.y * inv) * sc[1] + sh[1];
            o.z = (acc.z * inv) * sc[2] + sh[2];
            o.w = (acc.w * inv) * sc[3] + sh[3];
        }
        reinterpret_cast<uint2*>(HE)[(size_t)e * 64 + f4] =
            make_uint2(pack_h2(o.x, o.y), pack_h2(o.z, o.w));
    }
}

// node gather F=256 + bias + relu + fused BN-stats: HEW fp16 -> X1 fp16
__global__ void __launch_bounds__(256) k_node_gather_bn(const __half* __restrict__ HEW,
                                                        const float* __restrict__ bias,
                                                        __half* __restrict__ OUT) {
    __shared__ float rs[4][HID];
    __shared__ float rq[4][HID];
    int tid = threadIdx.x;
    int f4 = tid & 63;
    int sub = tid >> 6;              // 0..3
    int c = f4 * 4;
    float4 b4 = reinterpret_cast<const float4*>(bias)[f4];
    float s4[4] = {0.f, 0.f, 0.f, 0.f};
    float q4[4] = {0.f, 0.f, 0.f, 0.f};
    int base = blockIdx.x * 128;
#pragma unroll 4
    for (int i = 0; i < 32; i++) {
        int n = base + i * 4 + sub;
        if (n >= N_NODES) break;
        int s = g_nd_off[n], t = g_nd_off[n + 1];
        float4 acc = make_float4(0.f, 0.f, 0.f, 0.f);
        int j = s;
        for (; j + 4 <= t; j += 4) {
            int e0 = g_nd_hes[j], e1 = g_nd_hes[j + 1];
            int e2 = g_nd_hes[j + 2], e3 = g_nd_hes[j + 3];
            uint2 u0 = reinterpret_cast<const uint2*>(HEW)[(size_t)e0 * 64 + f4];
            uint2 u1 = reinterpret_cast<const uint2*>(HEW)[(size_t)e1 * 64 + f4];
            uint2 u2 = reinterpret_cast<const uint2*>(HEW)[(size_t)e2 * 64 + f4];
            uint2 u3 = reinterpret_cast<const uint2*>(HEW)[(size_t)e3 * 64 + f4];
            acc_h2(acc, u0); acc_h2(acc, u1); acc_h2(acc, u2); acc_h2(acc, u3);
        }
        for (; j < t; j++) {
            int e = g_nd_hes[j];
            acc_h2(acc, reinterpret_cast<const uint2*>(HEW)[(size_t)e * 64 + f4]);
        }
        float inv = (t > s) ? 1.0f / (float)(t - s) : 0.f;
        float4 o;
        o.x = fmaxf(fmaf(acc.x, inv, b4.x), 0.f);
        o.y = fmaxf(fmaf(acc.y, inv, b4.y), 0.f);
        o.z = fmaxf(fmaf(acc.z, inv, b4.z), 0.f);
        o.w = fmaxf(fmaf(acc.w, inv, b4.w), 0.f);
        reinterpret_cast<uint2*>(OUT)[(size_t)n * 64 + f4] =
            make_uint2(pack_h2(o.x, o.y), pack_h2(o.z, o.w));
        s4[0] += o.x; s4[1] += o.y; s4[2] += o.z; s4[3] += o.w;
        q4[0] += o.x * o.x; q4[1] += o.y * o.y; q4[2] += o.z * o.z; q4[3] += o.w * o.w;
    }
#pragma unroll
    for (int u = 0; u < 4; u++) {
        rs[sub][c + u] = s4[u];
        rq[sub][c + u] = q4[u];
    }
    __syncthreads();
    if (sub == 0) {
#pragma unroll
        for (int u = 0; u < 4; u++) {
            float ts = rs[0][c + u] + rs[1][c + u] + rs[2][c + u] + rs[3][c + u];
            float tq = rq[0][c + u] + rq[1][c + u] + rq[2][c + u] + rq[3][c + u];
            atomicAdd(&g_bnst[c + u], ts);
            atomicAdd(&g_bnst[HID + c + u], tq);
        }
    }
}

// node gather F=128 + bias + relu -> out fp32 (layer 3)
__global__ void __launch_bounds__(256) k_node_gather128(const __half* __restrict__ HEW,
                                                        const float* __restrict__ bias,
                                                        float* __restrict__ OUT) {
    int tid = threadIdx.x;
    int f4 = tid & 31;
    int sub = tid >> 5;              // 0..7
    float4 b4 = reinterpret_cast<const float4*>(bias)[f4];
    int base = blockIdx.x * 128;
#pragma unroll 4
    for (int i = 0; i < 16; i++) {
        int n = base + i * 8 + sub;
        if (n >= N_NODES) break;
        int s = g_nd_off[n], t = g_nd_off[n + 1];
        float4 acc = make_float4(0.f, 0.f, 0.f, 0.f);
        int j = s;
        for (; j + 4 <= t; j += 4) {
            int e0 = g_nd_hes[j], e1 = g_nd_hes[j + 1];
            int e2 = g_nd_hes[j + 2], e3 = g_nd_hes[j + 3];
            uint2 u0 = reinterpret_cast<const uint2*>(HEW)[(size_t)e0 * 32 + f4];
            uint2 u1 = reinterpret_cast<const uint2*>(HEW)[(size_t)e1 * 32 + f4];
            uint2 u2 = reinterpret_cast<const uint2*>(HEW)[(size_t)e2 * 32 + f4];
            uint2 u3 = reinterpret_cast<const uint2*>(HEW)[(size_t)e3 * 32 + f4];
            acc_h2(acc, u0); acc_h2(acc, u1); acc_h2(acc, u2); acc_h2(acc, u3);
        }
        for (; j < t; j++) {
            int e = g_nd_hes[j];
            acc_h2(acc, reinterpret_cast<const uint2*>(HEW)[(size_t)e * 32 + f4]);
        }
        float inv = (t > s) ? 1.0f / (float)(t - s) : 0.f;
        float4 o;
        o.x = fmaxf(fmaf(acc.x, inv, b4.x), 0.f);
        o.y = fmaxf(fmaf(acc.y, inv, b4.y), 0.f);
        o.z = fmaxf(fmaf(acc.z, inv, b4.z), 0.f);
        o.w = fmaxf(fmaf(acc.w, inv, b4.w), 0.f);
        reinterpret_cast<float4*>(OUT)[(size_t)n * 32 + f4] = o;
    }
}

// ---------------- launch ----------------
extern "C" void kernel_launch(void* const* d_in, const int* in_sizes, int n_in,
                              void* d_out, int out_size) {
    const float* x    = (const float*)d_in[0];
    const int*   edge = (const int*)d_in[1];
    const int*   node_idx = edge;
    const int*   he_idx   = edge + N_INC;
    const float* W1 = (const float*)d_in[2];
    const float* b1 = (const float*)d_in[3];
    const float* g1 = (const float*)d_in[4];
    const float* be1 = (const float*)d_in[5];
    const float* W2 = (const float*)d_in[6];
    const float* b2 = (const float*)d_in[7];
    const float* g2 = (const float*)d_in[8];
    const float* be2 = (const float*)d_in[9];
    const float* W3 = (const float*)d_in[10];
    const float* b3 = (const float*)d_in[11];
    float* out = (float*)d_out;

    void *p_X1, *p_HE, *p_HEW, *p_W1s, *p_W2s, *p_W3s;
    cudaGetSymbolAddress(&p_X1, g_X1);
    cudaGetSymbolAddress(&p_HE, g_HE);
    cudaGetSymbolAddress(&p_HEW, g_HEW);
    cudaGetSymbolAddress(&p_W1s, g_W1s);
    cudaGetSymbolAddress(&p_W2s, g_W2s);
    cudaGetSymbolAddress(&p_W3s, g_W3s);
    __half* X1  = (__half*)p_X1;
    __half* HE  = (__half*)p_HE;
    __half* HEW = (__half*)p_HEW;
    __half* W1s = (__half*)p_W1s;
    __half* W2s = (__half*)p_W2s;
    __half* W3s = (__half*)p_W3s;

    const int GEMM_SMEM_N256 = 2 * (16384 + 2 * 256 * 128);   // 163840
    const int GEMM_SMEM_N128 = 2 * (16384 + 2 * 128 * 128);   // 98304
    cudaFuncSetAttribute(gemm_f16<4>, cudaFuncAttributeMaxDynamicSharedMemorySize, GEMM_SMEM_N256);
    cudaFuncSetAttribute(gemm_f16<2>, cudaFuncAttributeMaxDynamicSharedMemorySize, GEMM_SMEM_N128);
    const int he_tiles = (N_HE + 127) / 128;      // 235
    const int he_g128 = (N_HE + 31) / 32;         // 938
    const int he_g256 = (N_HE + 15) / 16;         // 1875
    const int nd_g = (N_NODES + 127) / 128;       // 782

    // ---- weight splits + cnt zeroing (fused, one launch) ----
    k_split_W_all<<<512, 256>>>(W1, W2, W3);

    // ---- CSR build ----
    k_hist<<<(N_INC + 255) / 256, 256>>>(node_idx, he_idx);
    const int nb_nd = (N_NODES + 2047) / 2048;
    const int nb_he = (N_HE + 2047) / 2048;
    k_blk_sum2<<<nb_nd + nb_he, 256>>>(nb_nd);
    k_bsum_scan2<<<2, 1024>>>(nb_nd, nb_he);
    k_blk_scan2<<<nb_nd + nb_he, 256>>>(nb_nd);   // also re-zeroes cnt
    k_scatter<<<(N_INC + 255) / 256, 256>>>(node_idx, he_idx);

    // ---- layer 1: he_gather(x) -> GEMM -> node_gather+bn_stats ----
    {
        k_he_gather128<<<he_g128, 256>>>(x, HE);
        dim3 grid(1, he_tiles);
        gemm_f16<4><<<grid, 512, GEMM_SMEM_N256>>>(HE, W1s, HEW, N_HE, IN_CH);
        k_node_gather_bn<<<nd_g, 256>>>(HEW, b1, X1);
    }
    // ---- layer 2: he_gather(BN1 fused) -> GEMM -> node_gather+bn_stats ----
    {
        k_he_gather_bn<<<he_g256, 256>>>(X1, HE, g1, be1);
        dim3 grid(1, he_tiles);
        gemm_f16<4><<<grid, 512, GEMM_SMEM_N256>>>(HE, W2s, HEW, N_HE, HID);
        k_node_gather_bn<<<nd_g, 256>>>(HEW, b2, X1);
    }
    // ---- layer 3: he_gather(BN2 fused) -> GEMM(N=128) -> node_gather -> out ----
    {
        k_he_gather_bn<<<he_g256, 256>>>(X1, HE, g2, be2);
        dim3 grid(1, he_tiles);
        gemm_f16<2><<<grid, 256, GEMM_SMEM_N128>>>(HE, W3s, HEW, N_HE, HID);
        k_node_gather128<<<nd_g, 256>>>(HEW, b3, out);
    }
}